// round 11
// baseline (speedup 1.0000x reference)
#include <cuda_runtime.h>
#include <cuda_fp16.h>
#include <math.h>
#include <stdint.h>

#define B_   8
#define T_   1024
#define D_   768
#define H_   12
#define WIN_ 768
#define M_   (B_*T_)   // 8192

// ---------------- scratch (static device globals) ---------------------------
__device__ __half g_x1h[M_ * D_];
__device__ __half g_qkvh[M_ * 3 * D_];
__device__ __half g_attnh[M_ * D_];
__device__ float  g_x2[M_ * D_];
__device__ __half g_hh[M_ * 4 * D_];
__device__ __half g_wah[D_ * 3 * D_];
__device__ __half g_wph[D_ * D_];
__device__ __half g_wfh[D_ * 4 * D_];
__device__ __half g_wfph[4 * D_ * D_];

// ---------------- helpers -----------------------------------------------------
__device__ __forceinline__ uint32_t smem_to_u32(const void* p) {
    uint32_t a;
    asm("{ .reg .u64 t; cvta.to.shared.u64 t, %1; cvt.u32.u64 %0, t; }" : "=r"(a) : "l"(p));
    return a;
}
__device__ __forceinline__ uint32_t h2u(__half2 v) { return *(uint32_t*)&v; }

#define CP16(saddr, gptr) \
    asm volatile("cp.async.cg.shared.global [%0], [%1], 16;" :: "r"(saddr), "l"(gptr))
#define CP_COMMIT() asm volatile("cp.async.commit_group;" ::: "memory")
#define CP_WAIT1()  asm volatile("cp.async.wait_group 1;" ::: "memory")

#define LDSM4(r0, r1, r2, r3, addr) \
    asm volatile("ldmatrix.sync.aligned.m8n8.x4.shared.b16 {%0,%1,%2,%3}, [%4];" \
        : "=r"(r0), "=r"(r1), "=r"(r2), "=r"(r3) : "r"(addr))
#define LDSM4T(r0, r1, r2, r3, addr) \
    asm volatile("ldmatrix.sync.aligned.m8n8.x4.trans.shared.b16 {%0,%1,%2,%3}, [%4];" \
        : "=r"(r0), "=r"(r1), "=r"(r2), "=r"(r3) : "r"(addr))

__device__ __forceinline__ void mma1616(float* d, const uint32_t* a, const uint32_t* b) {
    asm volatile(
        "mma.sync.aligned.m16n8k16.row.col.f32.f16.f16.f32 "
        "{%0,%1,%2,%3}, {%4,%5,%6,%7}, {%8,%9}, {%0,%1,%2,%3};"
        : "+f"(d[0]), "+f"(d[1]), "+f"(d[2]), "+f"(d[3])
        : "r"(a[0]), "r"(a[1]), "r"(a[2]), "r"(a[3]), "r"(b[0]), "r"(b[1]));
}

// ---------------- fp16 tensor-core GEMM: 128x128 tile, BK=64 --------------------
// 3-stage cp.async pipeline, single sync per K-iter (12 iters for K=768).
enum { EPI_BIAS = 0, EPI_BIAS_RES = 1, EPI_BIAS_GELU = 2 };

#define NSTG 3
#define APADH 72                        // A tile row stride (halves), BK=64 + pad
#define BPADH 136                       // B tile row stride (halves)
#define A_ST (128 * APADH)              // 9216 halves
#define B_ST (64 * BPADH)               // 8704 halves
#define STG_H (A_ST + B_ST)             // 17920 halves = 35840 B
#define GEMM_SMEM (NSTG * STG_H * 2)    // 107520 B (x2 CTA = 210 KB <= 228 KB)

template <int EPI, bool OUTH>
__global__ void __launch_bounds__(256, 2) hgemm(
    const __half* __restrict__ A, const __half* __restrict__ W,
    const float* __restrict__ bias, const float* __restrict__ R,
    float* __restrict__ Cf, __half* __restrict__ Ch, int N, int K)
{
    extern __shared__ char dynsm[];
    __half* smh = (__half*)dynsm;
    const int tid = threadIdx.x;
    const int wid = tid >> 5, lane = tid & 31;
    const int wm = wid >> 2, wn = wid & 3;
    const int bm = blockIdx.y << 7, bn = blockIdx.x << 7;
    const int lr = lane >> 2, lc = lane & 3;
    const int arow = lane & 15, acol8 = (lane >> 4) * 8;
    const int sel = lane >> 3;
    const int brow = (sel & 1) * 8 + (lane & 7), bcol = (sel >> 1) * 8;
    const int NIT = K >> 6;

    const int am = tid >> 1, ac = tid & 1;     // A: row, 32-half chunk
    const int br = tid >> 4, bc = tid & 15;    // B: base row, col chunk
    const __half* gA = A + (size_t)(bm + am) * K + ac * 32;
    const __half* gB = W + (size_t)br * N + bn + bc * 8;

    float acc[4][4][4];
    #pragma unroll
    for (int i = 0; i < 4; i++)
        #pragma unroll
        for (int j = 0; j < 4; j++)
            #pragma unroll
            for (int k = 0; k < 4; k++) acc[i][j][k] = 0.f;

    auto load_stage = [&](int s, int kt) {
        __half* Ah = smh + s * STG_H;
        __half* Bh = Ah + A_ST;
        uint32_t sa = smem_to_u32(Ah + am * APADH + ac * 32);
        const __half* ga = gA + (kt << 6);
        CP16(sa,      ga);
        CP16(sa + 16, ga + 8);
        CP16(sa + 32, ga + 16);
        CP16(sa + 48, ga + 24);
        uint32_t sb = smem_to_u32(Bh + br * BPADH + bc * 8);
        const __half* gb = gB + (size_t)(kt << 6) * N;
        CP16(sb,                     gb);
        CP16(sb + 16 * BPADH * 2,    gb + (size_t)16 * N);
        CP16(sb + 32 * BPADH * 2,    gb + (size_t)32 * N);
        CP16(sb + 48 * BPADH * 2,    gb + (size_t)48 * N);
    };

    load_stage(0, 0); CP_COMMIT();
    load_stage(1, 1); CP_COMMIT();

    for (int it = 0; it < NIT; it++) {
        CP_WAIT1();
        __syncthreads();
        if (it + 2 < NIT) load_stage((it + 2) % NSTG, it + 2);
        CP_COMMIT();

        const __half* Ah = smh + (it % NSTG) * STG_H;
        const uint32_t abase = smem_to_u32(Ah);
        const uint32_t bbase = smem_to_u32(Ah + A_ST);
        #pragma unroll
        for (int kk = 0; kk < 4; kk++) {
            uint32_t bfr[4][2];
            #pragma unroll
            for (int ntp = 0; ntp < 2; ntp++) {
                uint32_t addr = bbase +
                    ((kk * 16 + brow) * BPADH + wn * 32 + ntp * 16 + bcol) * 2;
                LDSM4T(bfr[ntp * 2][0], bfr[ntp * 2][1],
                       bfr[ntp * 2 + 1][0], bfr[ntp * 2 + 1][1], addr);
            }
            #pragma unroll
            for (int mt = 0; mt < 4; mt++) {
                uint32_t af[4];
                uint32_t aaddr = abase +
                    ((wm * 64 + mt * 16 + arow) * APADH + kk * 16 + acol8) * 2;
                LDSM4(af[0], af[1], af[2], af[3], aaddr);
                #pragma unroll
                for (int nt = 0; nt < 4; nt++)
                    mma1616(acc[mt][nt], af, bfr[nt]);
            }
        }
    }

    #pragma unroll
    for (int mt = 0; mt < 4; mt++) {
        #pragma unroll
        for (int nt = 0; nt < 4; nt++) {
            int col = bn + wn * 32 + nt * 8 + lc * 2;
            float2 bv = *(const float2*)(bias + col);
            #pragma unroll
            for (int half = 0; half < 2; half++) {
                size_t row = (size_t)(bm + wm * 64 + mt * 16 + lr + half * 8);
                float v0 = acc[mt][nt][half * 2 + 0] + bv.x;
                float v1 = acc[mt][nt][half * 2 + 1] + bv.y;
                if (EPI == EPI_BIAS_RES) {
                    float2 rv = *(const float2*)(R + row * N + col);
                    v0 += rv.x; v1 += rv.y;
                }
                if (EPI == EPI_BIAS_GELU) {
                    v0 = 0.5f * v0 * (1.f + erff(v0 * 0.7071067811865476f));
                    v1 = 0.5f * v1 * (1.f + erff(v1 * 0.7071067811865476f));
                }
                if (OUTH) {
                    *(__half2*)(Ch + row * N + col) = __floats2half2_rn(v0, v1);
                } else {
                    float2 o = {v0, v1};
                    *(float2*)(Cf + row * N + col) = o;
                }
            }
        }
    }
}

// ---------------- all weights fp32 -> fp16, one launch ---------------------------
#define N4_0 (768 * 2304 / 4)
#define N4_1 (768 * 768 / 4)
#define N4_2 (768 * 3072 / 4)
#define N4_3 (3072 * 768 / 4)
#define N4_ALL (N4_0 + N4_1 + N4_2 + N4_3)

__global__ void cvt_all(const float4* __restrict__ w0, const float4* __restrict__ w1,
                        const float4* __restrict__ w2, const float4* __restrict__ w3,
                        __half2* __restrict__ o0, __half2* __restrict__ o1,
                        __half2* __restrict__ o2, __half2* __restrict__ o3) {
    int i = blockIdx.x * 256 + threadIdx.x;
    const float4* src;
    __half2* dst;
    int j = i;
    if (j < N4_0)                { src = w0; dst = o0; }
    else if ((j -= N4_0) < N4_1) { src = w1; dst = o1; }
    else if ((j -= N4_1) < N4_2) { src = w2; dst = o2; }
    else if ((j -= N4_2) < N4_3) { src = w3; dst = o3; }
    else return;
    float4 v = src[j];
    dst[j * 2]     = __floats2half2_rn(v.x, v.y);
    dst[j * 2 + 1] = __floats2half2_rn(v.z, v.w);
}

// ---------------- LayerNorm: warp per row, shfl-only reductions -------------------
__global__ void __launch_bounds__(256) ln_kernel(
    const float* __restrict__ x, const float* __restrict__ w,
    const float* __restrict__ bb, __half* __restrict__ y)
{
    const int warp = threadIdx.x >> 5, lane = threadIdx.x & 31;
    const size_t row = (size_t)blockIdx.x * 8 + warp;
    const float* xr = x + row * D_;

    float4 v[6];
    float s = 0.f;
    #pragma unroll
    for (int i = 0; i < 6; i++) {
        v[i] = *(const float4*)(xr + (i * 32 + lane) * 4);
        s += v[i].x + v[i].y + v[i].z + v[i].w;
    }
    #pragma unroll
    for (int o = 16; o > 0; o >>= 1) s += __shfl_xor_sync(0xffffffffu, s, o);
    const float mu = s * (1.f / 768.f);

    float vs = 0.f;
    #pragma unroll
    for (int i = 0; i < 6; i++) {
        v[i].x -= mu; v[i].y -= mu; v[i].z -= mu; v[i].w -= mu;
        vs += v[i].x * v[i].x + v[i].y * v[i].y + v[i].z * v[i].z + v[i].w * v[i].w;
    }
    #pragma unroll
    for (int o = 16; o > 0; o >>= 1) vs += __shfl_xor_sync(0xffffffffu, vs, o);
    const float rstd = rsqrtf(vs * (1.f / 768.f) + 1e-5f);

    __half* yr = y + row * D_;
    #pragma unroll
    for (int i = 0; i < 6; i++) {
        int c = (i * 32 + lane) * 4;
        float4 wv = *(const float4*)(w + c);
        float4 bv = *(const float4*)(bb + c);
        __half2 h0 = __floats2half2_rn(v[i].x * rstd * wv.x + bv.x,
                                       v[i].y * rstd * wv.y + bv.y);
        __half2 h1 = __floats2half2_rn(v[i].z * rstd * wv.z + bv.z,
                                       v[i].w * rstd * wv.w + bv.w);
        uint2 pack = {h2u(h0), h2u(h1)};
        *(uint2*)(yr + c) = pack;
    }
}

// ---------------- Attention: fp16 TC flash + cp.async K/V pipeline ----------------
// q-tile 128, key-tile 64, 3-slot pipeline; longest-work-first qi order.
#define TQ 128
#define QPH 72
#define KPH 72
#define VPH 72
#define KV_SLOT (64 * KPH + 64 * VPH)
#define ATTN_SMEM_BYTES ((128 * QPH + 3 * KV_SLOT) * 2 + 3 * 64 * 4 + 3 * 2 * 4 + 32)

__global__ void __launch_bounds__(256, 2) attn_h_kernel(
    const __half* __restrict__ qkv, const int* __restrict__ amask,
    __half* __restrict__ out)
{
    extern __shared__ char dynsm[];
    __half* Qs = (__half*)dynsm;
    __half* KV = Qs + 128 * QPH;
    int* kmsk  = (int*)(KV + 3 * KV_SLOT);
    int* mflag = kmsk + 3 * 64;

    // longest-work-first: high qi (most key tiles) scheduled first
    const int qi = (int)gridDim.x - 1 - (int)blockIdx.x;
    const int h = blockIdx.y, b = blockIdx.z;
    const int qb = qi * TQ;
    const int tid = threadIdx.x, wid = tid >> 5, lane = tid & 31;
    const int lr = lane >> 2, lc = lane & 3;
    const int wq = wid * 16;
    const int sel = lane >> 3;
    const int vrow = (sel & 1) * 8 + (lane & 7);
    const int vcol = (sel >> 1) * 8;
    const int krow = (lane & 7) + ((lane >> 4) << 3);
    const int kcol = ((lane >> 3) & 1) * 8;

    {
        int r = tid >> 1, cb = (tid & 1) * 32;
        const __half* src = qkv + (size_t)(b * T_ + qb + r) * (3 * D_) + h * 64 + cb;
        #pragma unroll
        for (int c = 0; c < 4; c++)
            *(uint4*)(Qs + r * QPH + cb + c * 8) = *(const uint4*)(src + c * 8);
    }

    int lo = qb - (WIN_ - 1);
    const int kt0 = (lo > 0 ? lo : 0) >> 6;
    const int kt1 = (qb + TQ - 1) >> 6;

    const int lrr = tid >> 2, lcb = (tid & 3) * 16;
    auto load_kv = [&](int s, int kt) {
        const int kb = kt * 64;
        __half* Kb = KV + s * KV_SLOT;
        __half* Vb = Kb + 64 * KPH;
        const __half* kp = qkv + (size_t)(b * T_ + kb + lrr) * (3 * D_) + D_ + h * 64 + lcb;
        uint32_t ka = smem_to_u32(Kb + lrr * KPH + lcb);
        uint32_t va = smem_to_u32(Vb + lrr * VPH + lcb);
        CP16(ka, kp);           CP16(ka + 16, kp + 8);
        CP16(va, kp + D_);      CP16(va + 16, kp + D_ + 8);
        if (tid < 64) {
            int mv = amask[b * T_ + kb + tid];
            kmsk[s * 64 + tid] = mv;
            unsigned bal = __ballot_sync(0xffffffffu, mv != 0);
            if ((tid & 31) == 0) mflag[s * 2 + (tid >> 5)] = (bal == 0xffffffffu);
        }
    };

    load_kv(0, kt0); CP_COMMIT();
    if (kt0 + 1 <= kt1) load_kv(1, kt0 + 1);
    CP_COMMIT();

    __syncthreads();
    const __half2 sc2 = __floats2half2_rn(0.125f, 0.125f);
    uint32_t qa[4][4];
    #pragma unroll
    for (int kk = 0; kk < 4; kk++) {
        const __half* p = Qs + (size_t)(wq + lr) * QPH + kk * 16 + lc * 2;
        qa[kk][0] = h2u(__hmul2(*(const __half2*)p, sc2));
        qa[kk][1] = h2u(__hmul2(*(const __half2*)(p + 8 * QPH), sc2));
        qa[kk][2] = h2u(__hmul2(*(const __half2*)(p + 8), sc2));
        qa[kk][3] = h2u(__hmul2(*(const __half2*)(p + 8 * QPH + 8), sc2));
    }

    float o[8][4];
    #pragma unroll
    for (int j = 0; j < 8; j++)
        #pragma unroll
        for (int k = 0; k < 4; k++) o[j][k] = 0.f;
    float mrow[2] = {-1e30f, -1e30f}, lrow[2] = {0.f, 0.f};

    for (int kt = kt0; kt <= kt1; kt++) {
        const int kb = kt * 64;
        const int s = (kt - kt0) % 3;

        CP_WAIT1();
        __syncthreads();
        if (kt + 2 <= kt1) load_kv((kt - kt0 + 2) % 3, kt + 2);
        CP_COMMIT();

        const __half* Kb = KV + s * KV_SLOT;
        const __half* Vb = Kb + 64 * KPH;
        const int* km = kmsk + s * 64;
        const bool tilefull = (kb + 63 <= qb) && (kb >= qb - 640) &&
                              mflag[s * 2] && mflag[s * 2 + 1];

        float sv[8][4];
        #pragma unroll
        for (int j = 0; j < 8; j++)
            sv[j][0] = sv[j][1] = sv[j][2] = sv[j][3] = 0.f;
        const uint32_t kbase = smem_to_u32(Kb);
        #pragma unroll
        for (int jp = 0; jp < 4; jp++) {
            #pragma unroll
            for (int kk = 0; kk < 4; kk++) {
                uint32_t kb4[4];
                uint32_t addr = kbase + ((jp * 16 + krow) * KPH + kk * 16 + kcol) * 2;
                LDSM4(kb4[0], kb4[1], kb4[2], kb4[3], addr);
                mma1616(sv[jp * 2],     qa[kk], kb4);
                mma1616(sv[jp * 2 + 1], qa[kk], kb4 + 2);
            }
        }

        if (!tilefull) {
            #pragma unroll
            for (int j = 0; j < 8; j++) {
                int kg0 = kb + j * 8 + lc * 2, kg1 = kg0 + 1;
                int km0 = km[j * 8 + lc * 2], km1 = km[j * 8 + lc * 2 + 1];
                #pragma unroll
                for (int half = 0; half < 2; half++) {
                    int qg = qb + wq + lr + half * 8;
                    bool v0 = (kg0 <= qg) && (kg0 > qg - WIN_) && (km0 != 0);
                    bool v1 = (kg1 <= qg) && (kg1 > qg - WIN_) && (km1 != 0);
                    if (!v0) sv[j][half * 2 + 0] = -1e30f;
                    if (!v1) sv[j][half * 2 + 1] = -1e30f;
                }
            }
        }

        float mnew[2], alpha[2], lsum[2];
        #pragma unroll
        for (int half = 0; half < 2; half++) {
            float m = -1e30f;
            #pragma unroll
            for (int j = 0; j < 8; j++)
                m = fmaxf(m, fmaxf(sv[j][half * 2], sv[j][half * 2 + 1]));
            m = fmaxf(m, __shfl_xor_sync(0xffffffffu, m, 1));
            m = fmaxf(m, __shfl_xor_sync(0xffffffffu, m, 2));
            mnew[half] = fmaxf(mrow[half], m);
            alpha[half] = __expf(mrow[half] - mnew[half]);
            lsum[half] = 0.f;
        }
        if (tilefull) {
            #pragma unroll
            for (int j = 0; j < 8; j++) {
                #pragma unroll
                for (int half = 0; half < 2; half++) {
                    float p0 = __expf(sv[j][half * 2]     - mnew[half]);
                    float p1 = __expf(sv[j][half * 2 + 1] - mnew[half]);
                    sv[j][half * 2] = p0; sv[j][half * 2 + 1] = p1;
                    lsum[half] += p0 + p1;
                }
            }
        } else {
            #pragma unroll
            for (int j = 0; j < 8; j++) {
                #pragma unroll
                for (int half = 0; half < 2; half++) {
                    float s0 = sv[j][half * 2], s1 = sv[j][half * 2 + 1];
                    float p0 = (s0 <= -1e29f) ? 0.f : __expf(s0 - mnew[half]);
                    float p1 = (s1 <= -1e29f) ? 0.f : __expf(s1 - mnew[half]);
                    sv[j][half * 2] = p0; sv[j][half * 2 + 1] = p1;
                    lsum[half] += p0 + p1;
                }
            }
        }
        #pragma unroll
        for (int half = 0; half < 2; half++) {
            lsum[half] += __shfl_xor_sync(0xffffffffu, lsum[half], 1);
            lsum[half] += __shfl_xor_sync(0xffffffffu, lsum[half], 2);
            lrow[half] = lrow[half] * alpha[half] + lsum[half];
            mrow[half] = mnew[half];
        }
        #pragma unroll
        for (int j = 0; j < 8; j++) {
            o[j][0] *= alpha[0]; o[j][1] *= alpha[0];
            o[j][2] *= alpha[1]; o[j][3] *= alpha[1];
        }

        const uint32_t vbase = smem_to_u32(Vb);
        #pragma unroll
        for (int kk = 0; kk < 4; kk++) {
            uint32_t pa[4] = {
                h2u(__floats2half2_rn(sv[2 * kk][0],     sv[2 * kk][1])),
                h2u(__floats2half2_rn(sv[2 * kk][2],     sv[2 * kk][3])),
                h2u(__floats2half2_rn(sv[2 * kk + 1][0], sv[2 * kk + 1][1])),
                h2u(__floats2half2_rn(sv[2 * kk + 1][2], sv[2 * kk + 1][3]))
            };
            #pragma unroll
            for (int jp = 0; jp < 4; jp++) {
                uint32_t vb[4];
                uint32_t addr = vbase + ((kk * 16 + vrow) * VPH + jp * 16 + vcol) * 2;
                LDSM4T(vb[0], vb[1], vb[2], vb[3], addr);
                mma1616(o[jp * 2],     pa, vb);
                mma1616(o[jp * 2 + 1], pa, vb + 2);
            }
        }
    }

    float linv[2] = {1.f / lrow[0], 1.f / lrow[1]};
    #pragma unroll
    for (int half = 0; half < 2; half++) {
        size_t row = (size_t)(b * T_ + qb + wq + lr + half * 8);
        __half* op = out + row * D_ + h * 64;
        #pragma unroll
        for (int j = 0; j < 8; j++)
            *(__half2*)(op + j * 8 + lc * 2) =
                __floats2half2_rn(o[j][half * 2] * linv[half], o[j][half * 2 + 1] * linv[half]);
    }
}

// ---------------- launch -----------------------------------------------------------
extern "C" void kernel_launch(void* const* d_in, const int* in_sizes, int n_in,
                              void* d_out, int out_size)
{
    const float* x      = (const float*)d_in[0];
    const int*   amask  = (const int*)d_in[1];
    const float* ln1_w  = (const float*)d_in[2];
    const float* ln1_b  = (const float*)d_in[3];
    const float* w_attn = (const float*)d_in[4];
    const float* b_attn = (const float*)d_in[5];
    const float* w_proj = (const float*)d_in[6];
    const float* b_proj = (const float*)d_in[7];
    const float* ln2_w  = (const float*)d_in[8];
    const float* ln2_b  = (const float*)d_in[9];
    const float* w_fc   = (const float*)d_in[10];
    const float* b_fc   = (const float*)d_in[11];
    const float* w_fcp  = (const float*)d_in[12];
    const float* b_fcp  = (const float*)d_in[13];
    float* out = (float*)d_out;

    __half *p_x1h, *p_qkvh, *p_attnh, *p_hh, *p_wah, *p_wph, *p_wfh, *p_wfph;
    float* p_x2;
    cudaGetSymbolAddress((void**)&p_x1h,   g_x1h);
    cudaGetSymbolAddress((void**)&p_qkvh,  g_qkvh);
    cudaGetSymbolAddress((void**)&p_attnh, g_attnh);
    cudaGetSymbolAddress((void**)&p_x2,    g_x2);
    cudaGetSymbolAddress((void**)&p_hh,    g_hh);
    cudaGetSymbolAddress((void**)&p_wah,   g_wah);
    cudaGetSymbolAddress((void**)&p_wph,   g_wph);
    cudaGetSymbolAddress((void**)&p_wfh,   g_wfh);
    cudaGetSymbolAddress((void**)&p_wfph,  g_wfph);

    cudaFuncSetAttribute(hgemm<EPI_BIAS, true>,       cudaFuncAttributeMaxDynamicSharedMemorySize, GEMM_SMEM);
    cudaFuncSetAttribute(hgemm<EPI_BIAS_RES, false>,  cudaFuncAttributeMaxDynamicSharedMemorySize, GEMM_SMEM);
    cudaFuncSetAttribute(hgemm<EPI_BIAS_GELU, true>,  cudaFuncAttributeMaxDynamicSharedMemorySize, GEMM_SMEM);
    cudaFuncSetAttribute(attn_h_kernel, cudaFuncAttributeMaxDynamicSharedMemorySize, ATTN_SMEM_BYTES);

    cvt_all<<<(N4_ALL + 255) / 256, 256>>>(
        (const float4*)w_attn, (const float4*)w_proj, (const float4*)w_fc, (const float4*)w_fcp,
        (__half2*)p_wah, (__half2*)p_wph, (__half2*)p_wfh, (__half2*)p_wfph);

    // 1) ln1 -> fp16
    ln_kernel<<<M_ / 8, 256>>>(x, ln1_w, ln1_b, p_x1h);
    // 2) qkv = x1 @ w_attn + b_attn
    hgemm<EPI_BIAS, true><<<dim3(2304 / 128, M_ / 128), 256, GEMM_SMEM>>>(
        p_x1h, p_wah, b_attn, nullptr, nullptr, p_qkvh, 2304, 768);
    // 3) attention (pipelined K/V, longest-first)
    attn_h_kernel<<<dim3(T_ / TQ, H_, B_), 256, ATTN_SMEM_BYTES>>>(p_qkvh, amask, p_attnh);
    // 4) x2 = attn @ w_proj + b_proj + x
    hgemm<EPI_BIAS_RES, false><<<dim3(768 / 128, M_ / 128), 256, GEMM_SMEM>>>(
        p_attnh, p_wph, b_proj, x, p_x2, nullptr, 768, 768);
    // 5) ln2 -> fp16
    ln_kernel<<<M_ / 8, 256>>>(p_x2, ln2_w, ln2_b, p_x1h);
    // 6) h = gelu(x1 @ w_fc + b_fc)
    hgemm<EPI_BIAS_GELU, true><<<dim3(3072 / 128, M_ / 128), 256, GEMM_SMEM>>>(
        p_x1h, p_wfh, b_fc, nullptr, nullptr, p_hh, 3072, 768);
    // 7) out = h @ w_fc_proj + b_fc_proj + x2
    hgemm<EPI_BIAS_RES, false><<<dim3(768 / 128, M_ / 128), 256, GEMM_SMEM>>>(
        p_hh, p_wfph, b_fcp, p_x2, out, nullptr, 768, 3072);
}

// round 12
// speedup vs baseline: 1.0813x; 1.0813x over previous
#include <cuda_runtime.h>
#include <cuda_fp16.h>
#include <math.h>
#include <stdint.h>

#define B_   8
#define T_   1024
#define D_   768
#define H_   12
#define WIN_ 768
#define M_   (B_*T_)   // 8192

// ---------------- scratch (static device globals) ---------------------------
__device__ __half g_x1h[M_ * D_];
__device__ __half g_qkvh[M_ * 3 * D_];
__device__ __half g_attnh[M_ * D_];
__device__ float  g_x2[M_ * D_];
__device__ __half g_hh[M_ * 4 * D_];
__device__ __half g_wah[D_ * 3 * D_];
__device__ __half g_wph[D_ * D_];
__device__ __half g_wfh[D_ * 4 * D_];
__device__ __half g_wfph[4 * D_ * D_];

// ---------------- helpers -----------------------------------------------------
__device__ __forceinline__ uint32_t smem_to_u32(const void* p) {
    uint32_t a;
    asm("{ .reg .u64 t; cvta.to.shared.u64 t, %1; cvt.u32.u64 %0, t; }" : "=r"(a) : "l"(p));
    return a;
}
__device__ __forceinline__ uint32_t h2u(__half2 v) { return *(uint32_t*)&v; }

#define CP16(saddr, gptr) \
    asm volatile("cp.async.cg.shared.global [%0], [%1], 16;" :: "r"(saddr), "l"(gptr))
#define CP_COMMIT() asm volatile("cp.async.commit_group;" ::: "memory")
#define CP_WAIT2()  asm volatile("cp.async.wait_group 2;" ::: "memory")
#define CP_WAIT1()  asm volatile("cp.async.wait_group 1;" ::: "memory")

#define LDSM4(r0, r1, r2, r3, addr) \
    asm volatile("ldmatrix.sync.aligned.m8n8.x4.shared.b16 {%0,%1,%2,%3}, [%4];" \
        : "=r"(r0), "=r"(r1), "=r"(r2), "=r"(r3) : "r"(addr))
#define LDSM4T(r0, r1, r2, r3, addr) \
    asm volatile("ldmatrix.sync.aligned.m8n8.x4.trans.shared.b16 {%0,%1,%2,%3}, [%4];" \
        : "=r"(r0), "=r"(r1), "=r"(r2), "=r"(r3) : "r"(addr))

__device__ __forceinline__ void mma1616(float* d, const uint32_t* a, const uint32_t* b) {
    asm volatile(
        "mma.sync.aligned.m16n8k16.row.col.f32.f16.f16.f32 "
        "{%0,%1,%2,%3}, {%4,%5,%6,%7}, {%8,%9}, {%0,%1,%2,%3};"
        : "+f"(d[0]), "+f"(d[1]), "+f"(d[2]), "+f"(d[3])
        : "r"(a[0]), "r"(a[1]), "r"(a[2]), "r"(a[3]), "r"(b[0]), "r"(b[1]));
}

// ---------------- fp16 tensor-core GEMM (round-10 config: 128x128, BK=32) -------
enum { EPI_BIAS = 0, EPI_BIAS_RES = 1, EPI_BIAS_GELU = 2 };

#define NSTG 4
#define APADH 40
#define BPADH 136
#define A_ST (128 * APADH)
#define B_ST (32 * BPADH)
#define STG_H (A_ST + B_ST)
#define GEMM_SMEM (NSTG * STG_H * 2)

template <int EPI, bool OUTH>
__global__ void __launch_bounds__(256, 2) hgemm(
    const __half* __restrict__ A, const __half* __restrict__ W,
    const float* __restrict__ bias, const float* __restrict__ R,
    float* __restrict__ Cf, __half* __restrict__ Ch, int N, int K)
{
    extern __shared__ char dynsm[];
    __half* smh = (__half*)dynsm;
    const int tid = threadIdx.x;
    const int wid = tid >> 5, lane = tid & 31;
    const int wm = wid >> 2, wn = wid & 3;
    const int bm = blockIdx.y << 7, bn = blockIdx.x << 7;
    const int lr = lane >> 2, lc = lane & 3;
    const int arow = lane & 15, acol8 = (lane >> 4) * 8;
    const int sel = lane >> 3;
    const int brow = (sel & 1) * 8 + (lane & 7), bcol = (sel >> 1) * 8;
    const int NIT = K >> 5;

    const int am = tid >> 1, ac = tid & 1;
    const int br = tid >> 4, bc = tid & 15;
    const __half* gA = A + (size_t)(bm + am) * K;
    const __half* gB = W + (size_t)br * N + bn;

    float acc[4][4][4];
    #pragma unroll
    for (int i = 0; i < 4; i++)
        #pragma unroll
        for (int j = 0; j < 4; j++)
            #pragma unroll
            for (int k = 0; k < 4; k++) acc[i][j][k] = 0.f;

    auto load_stage = [&](int s, int kt) {
        __half* Ah = smh + s * STG_H;
        __half* Bh = Ah + A_ST;
        uint32_t sa = smem_to_u32(Ah + am * APADH + ac * 16);
        const __half* ga = gA + (kt << 5) + ac * 16;
        CP16(sa, ga);
        CP16(sa + 16, ga + 8);
        uint32_t sb = smem_to_u32(Bh + br * BPADH + bc * 8);
        const __half* gb = gB + (size_t)(kt << 5) * N + bc * 8;
        CP16(sb, gb);
        CP16(sb + 16 * BPADH * 2, gb + (size_t)16 * N);
    };

    load_stage(0, 0); CP_COMMIT();
    load_stage(1, 1); CP_COMMIT();
    load_stage(2, 2); CP_COMMIT();

    for (int it = 0; it < NIT; it++) {
        CP_WAIT2();
        __syncthreads();
        if (it + 3 < NIT) load_stage((it + 3) % NSTG, it + 3);
        CP_COMMIT();

        const __half* Ah = smh + (it % NSTG) * STG_H;
        const uint32_t abase = smem_to_u32(Ah);
        const uint32_t bbase = smem_to_u32(Ah + A_ST);
        #pragma unroll
        for (int kk = 0; kk < 2; kk++) {
            uint32_t bfr[4][2];
            #pragma unroll
            for (int ntp = 0; ntp < 2; ntp++) {
                uint32_t addr = bbase +
                    ((kk * 16 + brow) * BPADH + wn * 32 + ntp * 16 + bcol) * 2;
                LDSM4T(bfr[ntp * 2][0], bfr[ntp * 2][1],
                       bfr[ntp * 2 + 1][0], bfr[ntp * 2 + 1][1], addr);
            }
            #pragma unroll
            for (int mt = 0; mt < 4; mt++) {
                uint32_t af[4];
                uint32_t aaddr = abase +
                    ((wm * 64 + mt * 16 + arow) * APADH + kk * 16 + acol8) * 2;
                LDSM4(af[0], af[1], af[2], af[3], aaddr);
                #pragma unroll
                for (int nt = 0; nt < 4; nt++)
                    mma1616(acc[mt][nt], af, bfr[nt]);
            }
        }
    }

    #pragma unroll
    for (int mt = 0; mt < 4; mt++) {
        #pragma unroll
        for (int nt = 0; nt < 4; nt++) {
            int col = bn + wn * 32 + nt * 8 + lc * 2;
            float2 bv = *(const float2*)(bias + col);
            #pragma unroll
            for (int half = 0; half < 2; half++) {
                size_t row = (size_t)(bm + wm * 64 + mt * 16 + lr + half * 8);
                float v0 = acc[mt][nt][half * 2 + 0] + bv.x;
                float v1 = acc[mt][nt][half * 2 + 1] + bv.y;
                if (EPI == EPI_BIAS_RES) {
                    float2 rv = *(const float2*)(R + row * N + col);
                    v0 += rv.x; v1 += rv.y;
                }
                if (EPI == EPI_BIAS_GELU) {
                    v0 = 0.5f * v0 * (1.f + erff(v0 * 0.7071067811865476f));
                    v1 = 0.5f * v1 * (1.f + erff(v1 * 0.7071067811865476f));
                }
                if (OUTH) {
                    *(__half2*)(Ch + row * N + col) = __floats2half2_rn(v0, v1);
                } else {
                    float2 o = {v0, v1};
                    *(float2*)(Cf + row * N + col) = o;
                }
            }
        }
    }
}

// ---------------- all weights fp32 -> fp16, one launch ---------------------------
#define N4_0 (768 * 2304 / 4)
#define N4_1 (768 * 768 / 4)
#define N4_2 (768 * 3072 / 4)
#define N4_3 (3072 * 768 / 4)
#define N4_ALL (N4_0 + N4_1 + N4_2 + N4_3)

__global__ void cvt_all(const float4* __restrict__ w0, const float4* __restrict__ w1,
                        const float4* __restrict__ w2, const float4* __restrict__ w3,
                        __half2* __restrict__ o0, __half2* __restrict__ o1,
                        __half2* __restrict__ o2, __half2* __restrict__ o3) {
    int i = blockIdx.x * 256 + threadIdx.x;
    const float4* src;
    __half2* dst;
    int j = i;
    if (j < N4_0)                { src = w0; dst = o0; }
    else if ((j -= N4_0) < N4_1) { src = w1; dst = o1; }
    else if ((j -= N4_1) < N4_2) { src = w2; dst = o2; }
    else if ((j -= N4_2) < N4_3) { src = w3; dst = o3; }
    else return;
    float4 v = src[j];
    dst[j * 2]     = __floats2half2_rn(v.x, v.y);
    dst[j * 2 + 1] = __floats2half2_rn(v.z, v.w);
}

// ---------------- LayerNorm: warp per row, shfl-only reductions -------------------
__global__ void __launch_bounds__(256) ln_kernel(
    const float* __restrict__ x, const float* __restrict__ w,
    const float* __restrict__ bb, __half* __restrict__ y)
{
    const int warp = threadIdx.x >> 5, lane = threadIdx.x & 31;
    const size_t row = (size_t)blockIdx.x * 8 + warp;
    const float* xr = x + row * D_;

    float4 v[6];
    float s = 0.f;
    #pragma unroll
    for (int i = 0; i < 6; i++) {
        v[i] = *(const float4*)(xr + (i * 32 + lane) * 4);
        s += v[i].x + v[i].y + v[i].z + v[i].w;
    }
    #pragma unroll
    for (int o = 16; o > 0; o >>= 1) s += __shfl_xor_sync(0xffffffffu, s, o);
    const float mu = s * (1.f / 768.f);

    float vs = 0.f;
    #pragma unroll
    for (int i = 0; i < 6; i++) {
        v[i].x -= mu; v[i].y -= mu; v[i].z -= mu; v[i].w -= mu;
        vs += v[i].x * v[i].x + v[i].y * v[i].y + v[i].z * v[i].z + v[i].w * v[i].w;
    }
    #pragma unroll
    for (int o = 16; o > 0; o >>= 1) vs += __shfl_xor_sync(0xffffffffu, vs, o);
    const float rstd = rsqrtf(vs * (1.f / 768.f) + 1e-5f);

    __half* yr = y + row * D_;
    #pragma unroll
    for (int i = 0; i < 6; i++) {
        int c = (i * 32 + lane) * 4;
        float4 wv = *(const float4*)(w + c);
        float4 bv = *(const float4*)(bb + c);
        __half2 h0 = __floats2half2_rn(v[i].x * rstd * wv.x + bv.x,
                                       v[i].y * rstd * wv.y + bv.y);
        __half2 h1 = __floats2half2_rn(v[i].z * rstd * wv.z + bv.z,
                                       v[i].w * rstd * wv.w + bv.w);
        uint2 pack = {h2u(h0), h2u(h1)};
        *(uint2*)(yr + c) = pack;
    }
}

// ---------------- Attention: fp16 TC flash + cp.async K/V pipeline ----------------
// q-tile 128, key-tile 64, 3-slot pipeline; per-warp fully-masked tile skip.
#define TQ 128
#define QPH 72
#define KPH 72
#define VPH 72
#define KV_SLOT (64 * KPH + 64 * VPH)
#define ATTN_SMEM_BYTES ((128 * QPH + 3 * KV_SLOT) * 2 + 3 * 64 * 4 + 3 * 2 * 4 + 32)

__global__ void __launch_bounds__(256, 2) attn_h_kernel(
    const __half* __restrict__ qkv, const int* __restrict__ amask,
    __half* __restrict__ out)
{
    extern __shared__ char dynsm[];
    __half* Qs = (__half*)dynsm;
    __half* KV = Qs + 128 * QPH;
    int* kmsk  = (int*)(KV + 3 * KV_SLOT);
    int* mflag = kmsk + 3 * 64;

    const int qi = blockIdx.x, h = blockIdx.y, b = blockIdx.z;
    const int qb = qi * TQ;
    const int tid = threadIdx.x, wid = tid >> 5, lane = tid & 31;
    const int lr = lane >> 2, lc = lane & 3;
    const int wq = wid * 16;
    const int sel = lane >> 3;
    const int vrow = (sel & 1) * 8 + (lane & 7);
    const int vcol = (sel >> 1) * 8;
    const int krow = (lane & 7) + ((lane >> 4) << 3);
    const int kcol = ((lane >> 3) & 1) * 8;

    {
        int r = tid >> 1, cb = (tid & 1) * 32;
        const __half* src = qkv + (size_t)(b * T_ + qb + r) * (3 * D_) + h * 64 + cb;
        #pragma unroll
        for (int c = 0; c < 4; c++)
            *(uint4*)(Qs + r * QPH + cb + c * 8) = *(const uint4*)(src + c * 8);
    }

    int lo = qb - (WIN_ - 1);
    const int kt0 = (lo > 0 ? lo : 0) >> 6;
    const int kt1 = (qb + TQ - 1) >> 6;

    const int lrr = tid >> 2, lcb = (tid & 3) * 16;
    auto load_kv = [&](int s, int kt) {
        const int kb = kt * 64;
        __half* Kb = KV + s * KV_SLOT;
        __half* Vb = Kb + 64 * KPH;
        const __half* kp = qkv + (size_t)(b * T_ + kb + lrr) * (3 * D_) + D_ + h * 64 + lcb;
        uint32_t ka = smem_to_u32(Kb + lrr * KPH + lcb);
        uint32_t va = smem_to_u32(Vb + lrr * VPH + lcb);
        CP16(ka, kp);           CP16(ka + 16, kp + 8);
        CP16(va, kp + D_);      CP16(va + 16, kp + D_ + 8);
        if (tid < 64) {
            int mv = amask[b * T_ + kb + tid];
            kmsk[s * 64 + tid] = mv;
            unsigned bal = __ballot_sync(0xffffffffu, mv != 0);
            if ((tid & 31) == 0) mflag[s * 2 + (tid >> 5)] = (bal == 0xffffffffu);
        }
    };

    load_kv(0, kt0); CP_COMMIT();
    if (kt0 + 1 <= kt1) load_kv(1, kt0 + 1);
    CP_COMMIT();

    __syncthreads();
    const __half2 sc2 = __floats2half2_rn(0.125f, 0.125f);
    uint32_t qa[4][4];
    #pragma unroll
    for (int kk = 0; kk < 4; kk++) {
        const __half* p = Qs + (size_t)(wq + lr) * QPH + kk * 16 + lc * 2;
        qa[kk][0] = h2u(__hmul2(*(const __half2*)p, sc2));
        qa[kk][1] = h2u(__hmul2(*(const __half2*)(p + 8 * QPH), sc2));
        qa[kk][2] = h2u(__hmul2(*(const __half2*)(p + 8), sc2));
        qa[kk][3] = h2u(__hmul2(*(const __half2*)(p + 8 * QPH + 8), sc2));
    }

    float o[8][4];
    #pragma unroll
    for (int j = 0; j < 8; j++)
        #pragma unroll
        for (int k = 0; k < 4; k++) o[j][k] = 0.f;
    float mrow[2] = {-1e30f, -1e30f}, lrow[2] = {0.f, 0.f};

    for (int kt = kt0; kt <= kt1; kt++) {
        const int kb = kt * 64;
        const int s = (kt - kt0) % 3;

        CP_WAIT1();
        __syncthreads();
        if (kt + 2 <= kt1) load_kv((kt - kt0 + 2) % 3, kt + 2);
        CP_COMMIT();

        // per-warp skip: tile contributes to this warp's queries at all?
        // valid key exists iff kb <= q_max (causal) and kb+63 > q_min-768 (window)
        const bool warp_active = (kb <= qb + wq + 15) && (kb + 63 > qb + wq - WIN_);
        if (warp_active) {
            const __half* Kb = KV + s * KV_SLOT;
            const __half* Vb = Kb + 64 * KPH;
            const int* km = kmsk + s * 64;
            const bool tilefull = (kb + 63 <= qb) && (kb >= qb - 640) &&
                                  mflag[s * 2] && mflag[s * 2 + 1];

            float sv[8][4];
            #pragma unroll
            for (int j = 0; j < 8; j++)
                sv[j][0] = sv[j][1] = sv[j][2] = sv[j][3] = 0.f;
            const uint32_t kbase = smem_to_u32(Kb);
            #pragma unroll
            for (int jp = 0; jp < 4; jp++) {
                #pragma unroll
                for (int kk = 0; kk < 4; kk++) {
                    uint32_t kb4[4];
                    uint32_t addr = kbase + ((jp * 16 + krow) * KPH + kk * 16 + kcol) * 2;
                    LDSM4(kb4[0], kb4[1], kb4[2], kb4[3], addr);
                    mma1616(sv[jp * 2],     qa[kk], kb4);
                    mma1616(sv[jp * 2 + 1], qa[kk], kb4 + 2);
                }
            }

            if (!tilefull) {
                #pragma unroll
                for (int j = 0; j < 8; j++) {
                    int kg0 = kb + j * 8 + lc * 2, kg1 = kg0 + 1;
                    int km0 = km[j * 8 + lc * 2], km1 = km[j * 8 + lc * 2 + 1];
                    #pragma unroll
                    for (int half = 0; half < 2; half++) {
                        int qg = qb + wq + lr + half * 8;
                        bool v0 = (kg0 <= qg) && (kg0 > qg - WIN_) && (km0 != 0);
                        bool v1 = (kg1 <= qg) && (kg1 > qg - WIN_) && (km1 != 0);
                        if (!v0) sv[j][half * 2 + 0] = -1e30f;
                        if (!v1) sv[j][half * 2 + 1] = -1e30f;
                    }
                }
            }

            float mnew[2], alpha[2], lsum[2];
            #pragma unroll
            for (int half = 0; half < 2; half++) {
                float m = -1e30f;
                #pragma unroll
                for (int j = 0; j < 8; j++)
                    m = fmaxf(m, fmaxf(sv[j][half * 2], sv[j][half * 2 + 1]));
                m = fmaxf(m, __shfl_xor_sync(0xffffffffu, m, 1));
                m = fmaxf(m, __shfl_xor_sync(0xffffffffu, m, 2));
                mnew[half] = fmaxf(mrow[half], m);
                alpha[half] = __expf(mrow[half] - mnew[half]);
                lsum[half] = 0.f;
            }
            if (tilefull) {
                #pragma unroll
                for (int j = 0; j < 8; j++) {
                    #pragma unroll
                    for (int half = 0; half < 2; half++) {
                        float p0 = __expf(sv[j][half * 2]     - mnew[half]);
                        float p1 = __expf(sv[j][half * 2 + 1] - mnew[half]);
                        sv[j][half * 2] = p0; sv[j][half * 2 + 1] = p1;
                        lsum[half] += p0 + p1;
                    }
                }
            } else {
                #pragma unroll
                for (int j = 0; j < 8; j++) {
                    #pragma unroll
                    for (int half = 0; half < 2; half++) {
                        float s0 = sv[j][half * 2], s1 = sv[j][half * 2 + 1];
                        float p0 = (s0 <= -1e29f) ? 0.f : __expf(s0 - mnew[half]);
                        float p1 = (s1 <= -1e29f) ? 0.f : __expf(s1 - mnew[half]);
                        sv[j][half * 2] = p0; sv[j][half * 2 + 1] = p1;
                        lsum[half] += p0 + p1;
                    }
                }
            }
            #pragma unroll
            for (int half = 0; half < 2; half++) {
                lsum[half] += __shfl_xor_sync(0xffffffffu, lsum[half], 1);
                lsum[half] += __shfl_xor_sync(0xffffffffu, lsum[half], 2);
                lrow[half] = lrow[half] * alpha[half] + lsum[half];
                mrow[half] = mnew[half];
            }
            #pragma unroll
            for (int j = 0; j < 8; j++) {
                o[j][0] *= alpha[0]; o[j][1] *= alpha[0];
                o[j][2] *= alpha[1]; o[j][3] *= alpha[1];
            }

            const uint32_t vbase = smem_to_u32(Vb);
            #pragma unroll
            for (int kk = 0; kk < 4; kk++) {
                uint32_t pa[4] = {
                    h2u(__floats2half2_rn(sv[2 * kk][0],     sv[2 * kk][1])),
                    h2u(__floats2half2_rn(sv[2 * kk][2],     sv[2 * kk][3])),
                    h2u(__floats2half2_rn(sv[2 * kk + 1][0], sv[2 * kk + 1][1])),
                    h2u(__floats2half2_rn(sv[2 * kk + 1][2], sv[2 * kk + 1][3]))
                };
                #pragma unroll
                for (int jp = 0; jp < 4; jp++) {
                    uint32_t vb[4];
                    uint32_t addr = vbase + ((kk * 16 + vrow) * VPH + jp * 16 + vcol) * 2;
                    LDSM4T(vb[0], vb[1], vb[2], vb[3], addr);
                    mma1616(o[jp * 2],     pa, vb);
                    mma1616(o[jp * 2 + 1], pa, vb + 2);
                }
            }
        }
    }

    float linv[2] = {1.f / lrow[0], 1.f / lrow[1]};
    #pragma unroll
    for (int half = 0; half < 2; half++) {
        size_t row = (size_t)(b * T_ + qb + wq + lr + half * 8);
        __half* op = out + row * D_ + h * 64;
        #pragma unroll
        for (int j = 0; j < 8; j++)
            *(__half2*)(op + j * 8 + lc * 2) =
                __floats2half2_rn(o[j][half * 2] * linv[half], o[j][half * 2 + 1] * linv[half]);
    }
}

// ---------------- launch -----------------------------------------------------------
extern "C" void kernel_launch(void* const* d_in, const int* in_sizes, int n_in,
                              void* d_out, int out_size)
{
    const float* x      = (const float*)d_in[0];
    const int*   amask  = (const int*)d_in[1];
    const float* ln1_w  = (const float*)d_in[2];
    const float* ln1_b  = (const float*)d_in[3];
    const float* w_attn = (const float*)d_in[4];
    const float* b_attn = (const float*)d_in[5];
    const float* w_proj = (const float*)d_in[6];
    const float* b_proj = (const float*)d_in[7];
    const float* ln2_w  = (const float*)d_in[8];
    const float* ln2_b  = (const float*)d_in[9];
    const float* w_fc   = (const float*)d_in[10];
    const float* b_fc   = (const float*)d_in[11];
    const float* w_fcp  = (const float*)d_in[12];
    const float* b_fcp  = (const float*)d_in[13];
    float* out = (float*)d_out;

    __half *p_x1h, *p_qkvh, *p_attnh, *p_hh, *p_wah, *p_wph, *p_wfh, *p_wfph;
    float* p_x2;
    cudaGetSymbolAddress((void**)&p_x1h,   g_x1h);
    cudaGetSymbolAddress((void**)&p_qkvh,  g_qkvh);
    cudaGetSymbolAddress((void**)&p_attnh, g_attnh);
    cudaGetSymbolAddress((void**)&p_x2,    g_x2);
    cudaGetSymbolAddress((void**)&p_hh,    g_hh);
    cudaGetSymbolAddress((void**)&p_wah,   g_wah);
    cudaGetSymbolAddress((void**)&p_wph,   g_wph);
    cudaGetSymbolAddress((void**)&p_wfh,   g_wfh);
    cudaGetSymbolAddress((void**)&p_wfph,  g_wfph);

    cudaFuncSetAttribute(hgemm<EPI_BIAS, true>,       cudaFuncAttributeMaxDynamicSharedMemorySize, GEMM_SMEM);
    cudaFuncSetAttribute(hgemm<EPI_BIAS_RES, false>,  cudaFuncAttributeMaxDynamicSharedMemorySize, GEMM_SMEM);
    cudaFuncSetAttribute(hgemm<EPI_BIAS_GELU, true>,  cudaFuncAttributeMaxDynamicSharedMemorySize, GEMM_SMEM);
    cudaFuncSetAttribute(attn_h_kernel, cudaFuncAttributeMaxDynamicSharedMemorySize, ATTN_SMEM_BYTES);

    cvt_all<<<(N4_ALL + 255) / 256, 256>>>(
        (const float4*)w_attn, (const float4*)w_proj, (const float4*)w_fc, (const float4*)w_fcp,
        (__half2*)p_wah, (__half2*)p_wph, (__half2*)p_wfh, (__half2*)p_wfph);

    // 1) ln1 -> fp16
    ln_kernel<<<M_ / 8, 256>>>(x, ln1_w, ln1_b, p_x1h);
    // 2) qkv = x1 @ w_attn + b_attn
    hgemm<EPI_BIAS, true><<<dim3(2304 / 128, M_ / 128), 256, GEMM_SMEM>>>(
        p_x1h, p_wah, b_attn, nullptr, nullptr, p_qkvh, 2304, 768);
    // 3) attention (pipelined K/V + per-warp tile skip)
    attn_h_kernel<<<dim3(T_ / TQ, H_, B_), 256, ATTN_SMEM_BYTES>>>(p_qkvh, amask, p_attnh);
    // 4) x2 = attn @ w_proj + b_proj + x
    hgemm<EPI_BIAS_RES, false><<<dim3(768 / 128, M_ / 128), 256, GEMM_SMEM>>>(
        p_attnh, p_wph, b_proj, x, p_x2, nullptr, 768, 768);
    // 5) ln2 -> fp16
    ln_kernel<<<M_ / 8, 256>>>(p_x2, ln2_w, ln2_b, p_x1h);
    // 6) h = gelu(x1 @ w_fc + b_fc)
    hgemm<EPI_BIAS_GELU, true><<<dim3(3072 / 128, M_ / 128), 256, GEMM_SMEM>>>(
        p_x1h, p_wfh, b_fc, nullptr, nullptr, p_hh, 3072, 768);
    // 7) out = h @ w_fc_proj + b_fc_proj + x2
    hgemm<EPI_BIAS_RES, false><<<dim3(768 / 128, M_ / 128), 256, GEMM_SMEM>>>(
        p_hh, p_wfph, b_fcp, p_x2, out, nullptr, 768, 3072);
}

// round 14
// speedup vs baseline: 1.0987x; 1.0161x over previous
#include <cuda_runtime.h>
#include <cuda_fp16.h>
#include <math.h>
#include <stdint.h>

#define B_   8
#define T_   1024
#define D_   768
#define H_   12
#define WIN_ 768
#define M_   (B_*T_)   // 8192
#define MASKNEG (-60000.0f)

// ---------------- scratch (static device globals) ---------------------------
__device__ __half g_x1h[M_ * D_];
__device__ __half g_qkvh[M_ * 3 * D_];
__device__ __half g_attnh[M_ * D_];
__device__ float  g_x2[M_ * D_];
__device__ __half g_hh[M_ * 4 * D_];
__device__ __half g_wah[D_ * 3 * D_];
__device__ __half g_wph[D_ * D_];
__device__ __half g_wfh[D_ * 4 * D_];
__device__ __half g_wfph[4 * D_ * D_];

// ---------------- helpers -----------------------------------------------------
__device__ __forceinline__ uint32_t smem_to_u32(const void* p) {
    uint32_t a;
    asm("{ .reg .u64 t; cvta.to.shared.u64 t, %1; cvt.u32.u64 %0, t; }" : "=r"(a) : "l"(p));
    return a;
}
__device__ __forceinline__ uint32_t h2u(__half2 v) { return *(uint32_t*)&v; }

#define CP16(saddr, gptr) \
    asm volatile("cp.async.cg.shared.global [%0], [%1], 16;" :: "r"(saddr), "l"(gptr))
#define CP_COMMIT() asm volatile("cp.async.commit_group;" ::: "memory")
#define CP_WAIT2()  asm volatile("cp.async.wait_group 2;" ::: "memory")
#define CP_WAIT1()  asm volatile("cp.async.wait_group 1;" ::: "memory")

#define LDSM4(r0, r1, r2, r3, addr) \
    asm volatile("ldmatrix.sync.aligned.m8n8.x4.shared.b16 {%0,%1,%2,%3}, [%4];" \
        : "=r"(r0), "=r"(r1), "=r"(r2), "=r"(r3) : "r"(addr))
#define LDSM4T(r0, r1, r2, r3, addr) \
    asm volatile("ldmatrix.sync.aligned.m8n8.x4.trans.shared.b16 {%0,%1,%2,%3}, [%4];" \
        : "=r"(r0), "=r"(r1), "=r"(r2), "=r"(r3) : "r"(addr))

__device__ __forceinline__ void mma1616(float* d, const uint32_t* a, const uint32_t* b) {
    asm volatile(
        "mma.sync.aligned.m16n8k16.row.col.f32.f16.f16.f32 "
        "{%0,%1,%2,%3}, {%4,%5,%6,%7}, {%8,%9}, {%0,%1,%2,%3};"
        : "+f"(d[0]), "+f"(d[1]), "+f"(d[2]), "+f"(d[3])
        : "r"(a[0]), "r"(a[1]), "r"(a[2]), "r"(a[3]), "r"(b[0]), "r"(b[1]));
}
__device__ __forceinline__ uint32_t ex2_h2(uint32_t x) {
    uint32_t r;
    asm("ex2.approx.f16x2 %0, %1;" : "=r"(r) : "r"(x));
    return r;
}

// ---------------- fp16 tensor-core GEMM (128x128, BK=32, 4 stages) --------------
enum { EPI_BIAS = 0, EPI_BIAS_RES = 1, EPI_BIAS_GELU = 2 };

#define NSTG 4
#define APADH 40
#define BPADH 136
#define A_ST (128 * APADH)
#define B_ST (32 * BPADH)
#define STG_H (A_ST + B_ST)
#define GEMM_SMEM (NSTG * STG_H * 2)

template <int EPI, bool OUTH>
__global__ void __launch_bounds__(256, 2) hgemm(
    const __half* __restrict__ A, const __half* __restrict__ W,
    const float* __restrict__ bias, const float* __restrict__ R,
    float* __restrict__ Cf, __half* __restrict__ Ch, int N, int K)
{
    extern __shared__ char dynsm[];
    __half* smh = (__half*)dynsm;
    const int tid = threadIdx.x;
    const int wid = tid >> 5, lane = tid & 31;
    const int wm = wid >> 2, wn = wid & 3;
    const int bm = blockIdx.y << 7, bn = blockIdx.x << 7;
    const int lr = lane >> 2, lc = lane & 3;
    const int arow = lane & 15, acol8 = (lane >> 4) * 8;
    const int sel = lane >> 3;
    const int brow = (sel & 1) * 8 + (lane & 7), bcol = (sel >> 1) * 8;
    const int NIT = K >> 5;

    const int am = tid >> 1, ac = tid & 1;
    const int br = tid >> 4, bc = tid & 15;
    const __half* gA = A + (size_t)(bm + am) * K;
    const __half* gB = W + (size_t)br * N + bn;

    float acc[4][4][4];
    #pragma unroll
    for (int i = 0; i < 4; i++)
        #pragma unroll
        for (int j = 0; j < 4; j++)
            #pragma unroll
            for (int k = 0; k < 4; k++) acc[i][j][k] = 0.f;

    auto load_stage = [&](int s, int kt) {
        __half* Ah = smh + s * STG_H;
        __half* Bh = Ah + A_ST;
        uint32_t sa = smem_to_u32(Ah + am * APADH + ac * 16);
        const __half* ga = gA + (kt << 5) + ac * 16;
        CP16(sa, ga);
        CP16(sa + 16, ga + 8);
        uint32_t sb = smem_to_u32(Bh + br * BPADH + bc * 8);
        const __half* gb = gB + (size_t)(kt << 5) * N + bc * 8;
        CP16(sb, gb);
        CP16(sb + 16 * BPADH * 2, gb + (size_t)16 * N);
    };

    load_stage(0, 0); CP_COMMIT();
    load_stage(1, 1); CP_COMMIT();
    load_stage(2, 2); CP_COMMIT();

    for (int it = 0; it < NIT; it++) {
        CP_WAIT2();
        __syncthreads();
        if (it + 3 < NIT) load_stage((it + 3) % NSTG, it + 3);
        CP_COMMIT();

        const __half* Ah = smh + (it % NSTG) * STG_H;
        const uint32_t abase = smem_to_u32(Ah);
        const uint32_t bbase = smem_to_u32(Ah + A_ST);
        #pragma unroll
        for (int kk = 0; kk < 2; kk++) {
            uint32_t bfr[4][2];
            #pragma unroll
            for (int ntp = 0; ntp < 2; ntp++) {
                uint32_t addr = bbase +
                    ((kk * 16 + brow) * BPADH + wn * 32 + ntp * 16 + bcol) * 2;
                LDSM4T(bfr[ntp * 2][0], bfr[ntp * 2][1],
                       bfr[ntp * 2 + 1][0], bfr[ntp * 2 + 1][1], addr);
            }
            #pragma unroll
            for (int mt = 0; mt < 4; mt++) {
                uint32_t af[4];
                uint32_t aaddr = abase +
                    ((wm * 64 + mt * 16 + arow) * APADH + kk * 16 + acol8) * 2;
                LDSM4(af[0], af[1], af[2], af[3], aaddr);
                #pragma unroll
                for (int nt = 0; nt < 4; nt++)
                    mma1616(acc[mt][nt], af, bfr[nt]);
            }
        }
    }

    #pragma unroll
    for (int mt = 0; mt < 4; mt++) {
        #pragma unroll
        for (int nt = 0; nt < 4; nt++) {
            int col = bn + wn * 32 + nt * 8 + lc * 2;
            float2 bv = *(const float2*)(bias + col);
            #pragma unroll
            for (int half = 0; half < 2; half++) {
                size_t row = (size_t)(bm + wm * 64 + mt * 16 + lr + half * 8);
                float v0 = acc[mt][nt][half * 2 + 0] + bv.x;
                float v1 = acc[mt][nt][half * 2 + 1] + bv.y;
                if (EPI == EPI_BIAS_RES) {
                    float2 rv = *(const float2*)(R + row * N + col);
                    v0 += rv.x; v1 += rv.y;
                }
                if (EPI == EPI_BIAS_GELU) {
                    v0 = 0.5f * v0 * (1.f + erff(v0 * 0.7071067811865476f));
                    v1 = 0.5f * v1 * (1.f + erff(v1 * 0.7071067811865476f));
                }
                if (OUTH) {
                    *(__half2*)(Ch + row * N + col) = __floats2half2_rn(v0, v1);
                } else {
                    float2 o = {v0, v1};
                    *(float2*)(Cf + row * N + col) = o;
                }
            }
        }
    }
}

// ---------------- all weights fp32 -> fp16, one launch ---------------------------
#define N4_0 (768 * 2304 / 4)
#define N4_1 (768 * 768 / 4)
#define N4_2 (768 * 3072 / 4)
#define N4_3 (3072 * 768 / 4)
#define N4_ALL (N4_0 + N4_1 + N4_2 + N4_3)

__global__ void cvt_all(const float4* __restrict__ w0, const float4* __restrict__ w1,
                        const float4* __restrict__ w2, const float4* __restrict__ w3,
                        __half2* __restrict__ o0, __half2* __restrict__ o1,
                        __half2* __restrict__ o2, __half2* __restrict__ o3) {
    int i = blockIdx.x * 256 + threadIdx.x;
    const float4* src;
    __half2* dst;
    int j = i;
    if (j < N4_0)                { src = w0; dst = o0; }
    else if ((j -= N4_0) < N4_1) { src = w1; dst = o1; }
    else if ((j -= N4_1) < N4_2) { src = w2; dst = o2; }
    else if ((j -= N4_2) < N4_3) { src = w3; dst = o3; }
    else return;
    float4 v = src[j];
    dst[j * 2]     = __floats2half2_rn(v.x, v.y);
    dst[j * 2 + 1] = __floats2half2_rn(v.z, v.w);
}

// ---------------- LayerNorm: warp per row, shfl-only reductions -------------------
__global__ void __launch_bounds__(256) ln_kernel(
    const float* __restrict__ x, const float* __restrict__ w,
    const float* __restrict__ bb, __half* __restrict__ y)
{
    const int warp = threadIdx.x >> 5, lane = threadIdx.x & 31;
    const size_t row = (size_t)blockIdx.x * 8 + warp;
    const float* xr = x + row * D_;

    float4 v[6];
    float s = 0.f;
    #pragma unroll
    for (int i = 0; i < 6; i++) {
        v[i] = *(const float4*)(xr + (i * 32 + lane) * 4);
        s += v[i].x + v[i].y + v[i].z + v[i].w;
    }
    #pragma unroll
    for (int o = 16; o > 0; o >>= 1) s += __shfl_xor_sync(0xffffffffu, s, o);
    const float mu = s * (1.f / 768.f);

    float vs = 0.f;
    #pragma unroll
    for (int i = 0; i < 6; i++) {
        v[i].x -= mu; v[i].y -= mu; v[i].z -= mu; v[i].w -= mu;
        vs += v[i].x * v[i].x + v[i].y * v[i].y + v[i].z * v[i].z + v[i].w * v[i].w;
    }
    #pragma unroll
    for (int o = 16; o > 0; o >>= 1) vs += __shfl_xor_sync(0xffffffffu, vs, o);
    const float rstd = rsqrtf(vs * (1.f / 768.f) + 1e-5f);

    __half* yr = y + row * D_;
    #pragma unroll
    for (int i = 0; i < 6; i++) {
        int c = (i * 32 + lane) * 4;
        float4 wv = *(const float4*)(w + c);
        float4 bv = *(const float4*)(bb + c);
        __half2 h0 = __floats2half2_rn(v[i].x * rstd * wv.x + bv.x,
                                       v[i].y * rstd * wv.y + bv.y);
        __half2 h1 = __floats2half2_rn(v[i].z * rstd * wv.z + bv.z,
                                       v[i].w * rstd * wv.w + bv.w);
        uint2 pack = {h2u(h0), h2u(h1)};
        *(uint2*)(yr + c) = pack;
    }
}

// ---------------- Attention: fp16 TC flash, ex2.f16x2 softmax, MMA lsum ----------
#define TQ 128
#define QPH 72
#define KPH 72
#define VPH 72
#define KV_SLOT (64 * KPH + 64 * VPH)
#define ATTN_SMEM_BYTES ((128 * QPH + 3 * KV_SLOT) * 2 + 3 * 64 * 4 + 3 * 2 * 4 + 64)

__global__ void __launch_bounds__(256, 2) attn_h_kernel(
    const __half* __restrict__ qkv, const int* __restrict__ amask,
    __half* __restrict__ out)
{
    extern __shared__ char dynsm[];
    __half* Qs = (__half*)dynsm;
    __half* KV = Qs + 128 * QPH;
    int* kmsk  = (int*)(KV + 3 * KV_SLOT);
    int* mflag = kmsk + 3 * 64;

    const int qi = blockIdx.x, h = blockIdx.y, b = blockIdx.z;
    const int qb = qi * TQ;
    const int tid = threadIdx.x, wid = tid >> 5, lane = tid & 31;
    const int lr = lane >> 2, lc = lane & 3;
    const int wq = wid * 16;
    const int sel = lane >> 3;
    const int vrow = (sel & 1) * 8 + (lane & 7);
    const int vcol = (sel >> 1) * 8;
    const int krow = (lane & 7) + ((lane >> 4) << 3);
    const int kcol = ((lane >> 3) & 1) * 8;

    {
        int r = tid >> 1, cb = (tid & 1) * 32;
        const __half* src = qkv + (size_t)(b * T_ + qb + r) * (3 * D_) + h * 64 + cb;
        #pragma unroll
        for (int c = 0; c < 4; c++)
            *(uint4*)(Qs + r * QPH + cb + c * 8) = *(const uint4*)(src + c * 8);
    }

    int lo = qb - (WIN_ - 1);
    const int kt0 = (lo > 0 ? lo : 0) >> 6;
    const int kt1 = (qb + TQ - 1) >> 6;

    const int lrr = tid >> 2, lcb = (tid & 3) * 16;
    auto load_kv = [&](int s, int kt) {
        const int kb = kt * 64;
        __half* Kb = KV + s * KV_SLOT;
        __half* Vb = Kb + 64 * KPH;
        const __half* kp = qkv + (size_t)(b * T_ + kb + lrr) * (3 * D_) + D_ + h * 64 + lcb;
        uint32_t ka = smem_to_u32(Kb + lrr * KPH + lcb);
        uint32_t va = smem_to_u32(Vb + lrr * VPH + lcb);
        CP16(ka, kp);           CP16(ka + 16, kp + 8);
        CP16(va, kp + D_);      CP16(va + 16, kp + D_ + 8);
        if (tid < 64) {
            Vb[tid * VPH + 64] = __float2half(1.f);   // ones column for lsum MMA
            int mv = amask[b * T_ + kb + tid];
            kmsk[s * 64 + tid] = mv;
            unsigned bal = __ballot_sync(0xffffffffu, mv != 0);
            if ((tid & 31) == 0) mflag[s * 2 + (tid >> 5)] = (bal == 0xffffffffu);
        }
    };

    load_kv(0, kt0); CP_COMMIT();
    if (kt0 + 1 <= kt1) load_kv(1, kt0 + 1);
    CP_COMMIT();

    __syncthreads();
    const __half2 sc2 = __floats2half2_rn(0.125f, 0.125f);
    uint32_t qa[4][4];
    #pragma unroll
    for (int kk = 0; kk < 4; kk++) {
        const __half* p = Qs + (size_t)(wq + lr) * QPH + kk * 16 + lc * 2;
        qa[kk][0] = h2u(__hmul2(*(const __half2*)p, sc2));
        qa[kk][1] = h2u(__hmul2(*(const __half2*)(p + 8 * QPH), sc2));
        qa[kk][2] = h2u(__hmul2(*(const __half2*)(p + 8), sc2));
        qa[kk][3] = h2u(__hmul2(*(const __half2*)(p + 8 * QPH + 8), sc2));
    }

    float o[8][4];
    #pragma unroll
    for (int j = 0; j < 8; j++)
        #pragma unroll
        for (int k = 0; k < 4; k++) o[j][k] = 0.f;
    float mrow[2] = {MASKNEG, MASKNEG}, lrow[2] = {0.f, 0.f};
    const float L2E = 1.4426950408889634f;

    for (int kt = kt0; kt <= kt1; kt++) {
        const int kb = kt * 64;
        const int s = (kt - kt0) % 3;

        CP_WAIT1();
        __syncthreads();
        if (kt + 2 <= kt1) load_kv((kt - kt0 + 2) % 3, kt + 2);
        CP_COMMIT();

        const bool warp_active = (kb <= qb + wq + 15) && (kb + 63 > qb + wq - WIN_);
        if (warp_active) {
            const __half* Kb = KV + s * KV_SLOT;
            const __half* Vb = Kb + 64 * KPH;
            const int* km = kmsk + s * 64;
            const bool tilefull = (kb + 63 <= qb + wq) && (kb >= qb + wq - 752) &&
                                  mflag[s * 2] && mflag[s * 2 + 1];

            float sv[8][4];
            #pragma unroll
            for (int j = 0; j < 8; j++)
                sv[j][0] = sv[j][1] = sv[j][2] = sv[j][3] = 0.f;
            const uint32_t kbase = smem_to_u32(Kb);
            #pragma unroll
            for (int jp = 0; jp < 4; jp++) {
                #pragma unroll
                for (int kk = 0; kk < 4; kk++) {
                    uint32_t kb4[4];
                    uint32_t addr = kbase + ((jp * 16 + krow) * KPH + kk * 16 + kcol) * 2;
                    LDSM4(kb4[0], kb4[1], kb4[2], kb4[3], addr);
                    mma1616(sv[jp * 2],     qa[kk], kb4);
                    mma1616(sv[jp * 2 + 1], qa[kk], kb4 + 2);
                }
            }

            if (!tilefull) {
                #pragma unroll
                for (int j = 0; j < 8; j++) {
                    int kg0 = kb + j * 8 + lc * 2, kg1 = kg0 + 1;
                    int km0 = km[j * 8 + lc * 2], km1 = km[j * 8 + lc * 2 + 1];
                    #pragma unroll
                    for (int half = 0; half < 2; half++) {
                        int qg = qb + wq + lr + half * 8;
                        bool v0 = (kg0 <= qg) && (kg0 > qg - WIN_) && (km0 != 0);
                        bool v1 = (kg1 <= qg) && (kg1 > qg - WIN_) && (km1 != 0);
                        if (!v0) sv[j][half * 2 + 0] = MASKNEG;
                        if (!v1) sv[j][half * 2 + 1] = MASKNEG;
                    }
                }
            }

            // max reduction (fp32)
            float mnew[2], alpha[2];
            #pragma unroll
            for (int half = 0; half < 2; half++) {
                float m = MASKNEG;
                #pragma unroll
                for (int j = 0; j < 8; j++)
                    m = fmaxf(m, fmaxf(sv[j][half * 2], sv[j][half * 2 + 1]));
                m = fmaxf(m, __shfl_xor_sync(0xffffffffu, m, 1));
                m = fmaxf(m, __shfl_xor_sync(0xffffffffu, m, 2));
                mnew[half] = fmaxf(mrow[half], m);
                alpha[half] = __expf(mrow[half] - mnew[half]);
            }

            // p = 2^((s - m)*log2e) via f16x2 MUFU; results ARE the PV fragments.
            // Masked s = -60000 -> t ~ -8.6e4 -> fp16 -inf -> ex2 = 0 exactly.
            const float nm0 = mnew[0] * L2E, nm1 = mnew[1] * L2E;
            uint32_t pu[8][2];
            #pragma unroll
            for (int j = 0; j < 8; j++) {
                float t0 = fmaf(sv[j][0], L2E, -nm0);
                float t1 = fmaf(sv[j][1], L2E, -nm0);
                float t2 = fmaf(sv[j][2], L2E, -nm1);
                float t3 = fmaf(sv[j][3], L2E, -nm1);
                pu[j][0] = ex2_h2(h2u(__floats2half2_rn(t0, t1)));
                pu[j][1] = ex2_h2(h2u(__floats2half2_rn(t2, t3)));
            }

            #pragma unroll
            for (int j = 0; j < 8; j++) {
                o[j][0] *= alpha[0]; o[j][1] *= alpha[0];
                o[j][2] *= alpha[1]; o[j][3] *= alpha[1];
            }

            // O += P V ; lsum via ones-column MMA (col 64)
            float ls[4] = {0.f, 0.f, 0.f, 0.f};
            const uint32_t vbase = smem_to_u32(Vb);
            #pragma unroll
            for (int kk = 0; kk < 4; kk++) {
                uint32_t pa[4] = {pu[2 * kk][0], pu[2 * kk][1],
                                  pu[2 * kk + 1][0], pu[2 * kk + 1][1]};
                #pragma unroll
                for (int jp = 0; jp < 4; jp++) {
                    uint32_t vb[4];
                    uint32_t addr = vbase + ((kk * 16 + vrow) * VPH + jp * 16 + vcol) * 2;
                    LDSM4T(vb[0], vb[1], vb[2], vb[3], addr);
                    mma1616(o[jp * 2],     pa, vb);
                    mma1616(o[jp * 2 + 1], pa, vb + 2);
                }
                uint32_t vb1[4];
                uint32_t addr1 = vbase + ((kk * 16 + vrow) * VPH + 64 + vcol) * 2;
                LDSM4T(vb1[0], vb1[1], vb1[2], vb1[3], addr1);
                mma1616(ls, pa, vb1);
            }
            float l0 = __shfl_sync(0xffffffffu, ls[0], lane & 0x1c);
            float l1 = __shfl_sync(0xffffffffu, ls[2], lane & 0x1c);
            lrow[0] = lrow[0] * alpha[0] + l0;
            lrow[1] = lrow[1] * alpha[1] + l1;
            mrow[0] = mnew[0];
            mrow[1] = mnew[1];
        }
    }

    float linv[2] = {1.f / lrow[0], 1.f / lrow[1]};
    #pragma unroll
    for (int half = 0; half < 2; half++) {
        size_t row = (size_t)(b * T_ + qb + wq + lr + half * 8);
        __half* op = out + row * D_ + h * 64;
        #pragma unroll
        for (int j = 0; j < 8; j++)
            *(__half2*)(op + j * 8 + lc * 2) =
                __floats2half2_rn(o[j][half * 2] * linv[half], o[j][half * 2 + 1] * linv[half]);
    }
}

// ---------------- launch -----------------------------------------------------------
extern "C" void kernel_launch(void* const* d_in, const int* in_sizes, int n_in,
                              void* d_out, int out_size)
{
    const float* x      = (const float*)d_in[0];
    const int*   amask  = (const int*)d_in[1];
    const float* ln1_w  = (const float*)d_in[2];
    const float* ln1_b  = (const float*)d_in[3];
    const float* w_attn = (const float*)d_in[4];
    const float* b_attn = (const float*)d_in[5];
    const float* w_proj = (const float*)d_in[6];
    const float* b_proj = (const float*)d_in[7];
    const float* ln2_w  = (const float*)d_in[8];
    const float* ln2_b  = (const float*)d_in[9];
    const float* w_fc   = (const float*)d_in[10];
    const float* b_fc   = (const float*)d_in[11];
    const float* w_fcp  = (const float*)d_in[12];
    const float* b_fcp  = (const float*)d_in[13];
    float* out = (float*)d_out;

    __half *p_x1h, *p_qkvh, *p_attnh, *p_hh, *p_wah, *p_wph, *p_wfh, *p_wfph;
    float* p_x2;
    cudaGetSymbolAddress((void**)&p_x1h,   g_x1h);
    cudaGetSymbolAddress((void**)&p_qkvh,  g_qkvh);
    cudaGetSymbolAddress((void**)&p_attnh, g_attnh);
    cudaGetSymbolAddress((void**)&p_x2,    g_x2);
    cudaGetSymbolAddress((void**)&p_hh,    g_hh);
    cudaGetSymbolAddress((void**)&p_wah,   g_wah);
    cudaGetSymbolAddress((void**)&p_wph,   g_wph);
    cudaGetSymbolAddress((void**)&p_wfh,   g_wfh);
    cudaGetSymbolAddress((void**)&p_wfph,  g_wfph);

    cudaFuncSetAttribute(hgemm<EPI_BIAS, true>,       cudaFuncAttributeMaxDynamicSharedMemorySize, GEMM_SMEM);
    cudaFuncSetAttribute(hgemm<EPI_BIAS_RES, false>,  cudaFuncAttributeMaxDynamicSharedMemorySize, GEMM_SMEM);
    cudaFuncSetAttribute(hgemm<EPI_BIAS_GELU, true>,  cudaFuncAttributeMaxDynamicSharedMemorySize, GEMM_SMEM);
    cudaFuncSetAttribute(attn_h_kernel, cudaFuncAttributeMaxDynamicSharedMemorySize, ATTN_SMEM_BYTES);

    cvt_all<<<(N4_ALL + 255) / 256, 256>>>(
        (const float4*)w_attn, (const float4*)w_proj, (const float4*)w_fc, (const float4*)w_fcp,
        (__half2*)p_wah, (__half2*)p_wph, (__half2*)p_wfh, (__half2*)p_wfph);

    // 1) ln1 -> fp16
    ln_kernel<<<M_ / 8, 256>>>(x, ln1_w, ln1_b, p_x1h);
    // 2) qkv = x1 @ w_attn + b_attn
    hgemm<EPI_BIAS, true><<<dim3(2304 / 128, M_ / 128), 256, GEMM_SMEM>>>(
        p_x1h, p_wah, b_attn, nullptr, nullptr, p_qkvh, 2304, 768);
    // 3) attention
    attn_h_kernel<<<dim3(T_ / TQ, H_, B_), 256, ATTN_SMEM_BYTES>>>(p_qkvh, amask, p_attnh);
    // 4) x2 = attn @ w_proj + b_proj + x
    hgemm<EPI_BIAS_RES, false><<<dim3(768 / 128, M_ / 128), 256, GEMM_SMEM>>>(
        p_attnh, p_wph, b_proj, x, p_x2, nullptr, 768, 768);
    // 5) ln2 -> fp16
    ln_kernel<<<M_ / 8, 256>>>(p_x2, ln2_w, ln2_b, p_x1h);
    // 6) h = gelu(x1 @ w_fc + b_fc)
    hgemm<EPI_BIAS_GELU, true><<<dim3(3072 / 128, M_ / 128), 256, GEMM_SMEM>>>(
        p_x1h, p_wfh, b_fc, nullptr, nullptr, p_hh, 3072, 768);
    // 7) out = h @ w_fc_proj + b_fc_proj + x2
    hgemm<EPI_BIAS_RES, false><<<dim3(768 / 128, M_ / 128), 256, GEMM_SMEM>>>(
        p_hh, p_wfph, b_fcp, p_x2, out, nullptr, 768, 3072);
}

// round 15
// speedup vs baseline: 1.0997x; 1.0009x over previous
#include <cuda_runtime.h>
#include <cuda_fp16.h>
#include <math.h>
#include <stdint.h>

#define B_   8
#define T_   1024
#define D_   768
#define H_   12
#define WIN_ 768
#define M_   (B_*T_)   // 8192
#define MASKNEG (-60000.0f)

// ---------------- scratch (static device globals) ---------------------------
__device__ __half g_x1h[M_ * D_];
__device__ __half g_qkvh[M_ * 3 * D_];
__device__ __half g_attnh[M_ * D_];
__device__ float  g_x2[M_ * D_];
__device__ __half g_hh[M_ * 4 * D_];
__device__ __half g_wah[D_ * 3 * D_];
__device__ __half g_wph[D_ * D_];
__device__ __half g_wfh[D_ * 4 * D_];
__device__ __half g_wfph[4 * D_ * D_];

// ---------------- helpers -----------------------------------------------------
__device__ __forceinline__ uint32_t smem_to_u32(const void* p) {
    uint32_t a;
    asm("{ .reg .u64 t; cvta.to.shared.u64 t, %1; cvt.u32.u64 %0, t; }" : "=r"(a) : "l"(p));
    return a;
}
__device__ __forceinline__ uint32_t h2u(__half2 v) { return *(uint32_t*)&v; }

#define CP16(saddr, gptr) \
    asm volatile("cp.async.cg.shared.global [%0], [%1], 16;" :: "r"(saddr), "l"(gptr))
#define CP_COMMIT() asm volatile("cp.async.commit_group;" ::: "memory")
#define CP_WAIT2()  asm volatile("cp.async.wait_group 2;" ::: "memory")
#define CP_WAIT1()  asm volatile("cp.async.wait_group 1;" ::: "memory")

#define LDSM4(r0, r1, r2, r3, addr) \
    asm volatile("ldmatrix.sync.aligned.m8n8.x4.shared.b16 {%0,%1,%2,%3}, [%4];" \
        : "=r"(r0), "=r"(r1), "=r"(r2), "=r"(r3) : "r"(addr))
#define LDSM4T(r0, r1, r2, r3, addr) \
    asm volatile("ldmatrix.sync.aligned.m8n8.x4.trans.shared.b16 {%0,%1,%2,%3}, [%4];" \
        : "=r"(r0), "=r"(r1), "=r"(r2), "=r"(r3) : "r"(addr))

__device__ __forceinline__ void mma1616(float* d, const uint32_t* a, const uint32_t* b) {
    asm volatile(
        "mma.sync.aligned.m16n8k16.row.col.f32.f16.f16.f32 "
        "{%0,%1,%2,%3}, {%4,%5,%6,%7}, {%8,%9}, {%0,%1,%2,%3};"
        : "+f"(d[0]), "+f"(d[1]), "+f"(d[2]), "+f"(d[3])
        : "r"(a[0]), "r"(a[1]), "r"(a[2]), "r"(a[3]), "r"(b[0]), "r"(b[1]));
}
__device__ __forceinline__ uint32_t ex2_h2(uint32_t x) {
    uint32_t r;
    asm("ex2.approx.f16x2 %0, %1;" : "=r"(r) : "r"(x));
    return r;
}

// ---------------- fp16 tensor-core GEMM (128x128, BK=32, 4 stages) --------------
// EPI_RED: split-K partial; atomicAdd fp32 into pre-initialized C (no bias/R).
enum { EPI_BIAS = 0, EPI_BIAS_RES = 1, EPI_BIAS_GELU = 2, EPI_RED = 3 };

#define NSTG 4
#define APADH 40
#define BPADH 136
#define A_ST (128 * APADH)
#define B_ST (32 * BPADH)
#define STG_H (A_ST + B_ST)
#define GEMM_SMEM (NSTG * STG_H * 2)

template <int EPI, bool OUTH>
__global__ void __launch_bounds__(256, 2) hgemm(
    const __half* __restrict__ A, const __half* __restrict__ W,
    const float* __restrict__ bias, const float* __restrict__ R,
    float* __restrict__ Cf, __half* __restrict__ Ch, int N, int K, int Kstride)
{
    extern __shared__ char dynsm[];
    __half* smh = (__half*)dynsm;
    const int tid = threadIdx.x;
    const int wid = tid >> 5, lane = tid & 31;
    const int wm = wid >> 2, wn = wid & 3;
    const int bm = blockIdx.y << 7, bn = blockIdx.x << 7;
    const int koff = blockIdx.z * K;
    const int lr = lane >> 2, lc = lane & 3;
    const int arow = lane & 15, acol8 = (lane >> 4) * 8;
    const int sel = lane >> 3;
    const int brow = (sel & 1) * 8 + (lane & 7), bcol = (sel >> 1) * 8;
    const int NIT = K >> 5;

    const int am = tid >> 1, ac = tid & 1;
    const int br = tid >> 4, bc = tid & 15;
    const __half* gA = A + (size_t)(bm + am) * Kstride + koff;
    const __half* gB = W + (size_t)(koff + br) * N + bn;

    float acc[4][4][4];
    #pragma unroll
    for (int i = 0; i < 4; i++)
        #pragma unroll
        for (int j = 0; j < 4; j++)
            #pragma unroll
            for (int k = 0; k < 4; k++) acc[i][j][k] = 0.f;

    auto load_stage = [&](int s, int kt) {
        __half* Ah = smh + s * STG_H;
        __half* Bh = Ah + A_ST;
        uint32_t sa = smem_to_u32(Ah + am * APADH + ac * 16);
        const __half* ga = gA + (kt << 5) + ac * 16;
        CP16(sa, ga);
        CP16(sa + 16, ga + 8);
        uint32_t sb = smem_to_u32(Bh + br * BPADH + bc * 8);
        const __half* gb = gB + (size_t)(kt << 5) * N + bc * 8;
        CP16(sb, gb);
        CP16(sb + 16 * BPADH * 2, gb + (size_t)16 * N);
    };

    load_stage(0, 0); CP_COMMIT();
    load_stage(1, 1); CP_COMMIT();
    load_stage(2, 2); CP_COMMIT();

    for (int it = 0; it < NIT; it++) {
        CP_WAIT2();
        __syncthreads();
        if (it + 3 < NIT) load_stage((it + 3) % NSTG, it + 3);
        CP_COMMIT();

        const __half* Ah = smh + (it % NSTG) * STG_H;
        const uint32_t abase = smem_to_u32(Ah);
        const uint32_t bbase = smem_to_u32(Ah + A_ST);
        #pragma unroll
        for (int kk = 0; kk < 2; kk++) {
            uint32_t bfr[4][2];
            #pragma unroll
            for (int ntp = 0; ntp < 2; ntp++) {
                uint32_t addr = bbase +
                    ((kk * 16 + brow) * BPADH + wn * 32 + ntp * 16 + bcol) * 2;
                LDSM4T(bfr[ntp * 2][0], bfr[ntp * 2][1],
                       bfr[ntp * 2 + 1][0], bfr[ntp * 2 + 1][1], addr);
            }
            #pragma unroll
            for (int mt = 0; mt < 4; mt++) {
                uint32_t af[4];
                uint32_t aaddr = abase +
                    ((wm * 64 + mt * 16 + arow) * APADH + kk * 16 + acol8) * 2;
                LDSM4(af[0], af[1], af[2], af[3], aaddr);
                #pragma unroll
                for (int nt = 0; nt < 4; nt++)
                    mma1616(acc[mt][nt], af, bfr[nt]);
            }
        }
    }

    #pragma unroll
    for (int mt = 0; mt < 4; mt++) {
        #pragma unroll
        for (int nt = 0; nt < 4; nt++) {
            int col = bn + wn * 32 + nt * 8 + lc * 2;
            float2 bv = {0.f, 0.f};
            if (EPI != EPI_RED) bv = *(const float2*)(bias + col);
            #pragma unroll
            for (int half = 0; half < 2; half++) {
                size_t row = (size_t)(bm + wm * 64 + mt * 16 + lr + half * 8);
                float v0 = acc[mt][nt][half * 2 + 0] + bv.x;
                float v1 = acc[mt][nt][half * 2 + 1] + bv.y;
                if (EPI == EPI_BIAS_RES) {
                    float2 rv = *(const float2*)(R + row * N + col);
                    v0 += rv.x; v1 += rv.y;
                }
                if (EPI == EPI_BIAS_GELU) {
                    v0 = 0.5f * v0 * (1.f + erff(v0 * 0.7071067811865476f));
                    v1 = 0.5f * v1 * (1.f + erff(v1 * 0.7071067811865476f));
                }
                if (EPI == EPI_RED) {
                    atomicAdd(Cf + row * N + col,     v0);
                    atomicAdd(Cf + row * N + col + 1, v1);
                } else if (OUTH) {
                    *(__half2*)(Ch + row * N + col) = __floats2half2_rn(v0, v1);
                } else {
                    float2 o = {v0, v1};
                    *(float2*)(Cf + row * N + col) = o;
                }
            }
        }
    }
}

// ---------------- out init: out = x2 + bias (per column) -------------------------
__global__ void init_out_kernel(const float4* __restrict__ x2,
                                const float* __restrict__ bias,
                                float4* __restrict__ out) {
    int i = blockIdx.x * 256 + threadIdx.x;          // i indexes float4
    int col = (i * 4) % D_;
    float4 v = x2[i];
    float4 bv = *(const float4*)(bias + col);
    v.x += bv.x; v.y += bv.y; v.z += bv.z; v.w += bv.w;
    out[i] = v;
}

// ---------------- all weights fp32 -> fp16, one launch ---------------------------
#define N4_0 (768 * 2304 / 4)
#define N4_1 (768 * 768 / 4)
#define N4_2 (768 * 3072 / 4)
#define N4_3 (3072 * 768 / 4)
#define N4_ALL (N4_0 + N4_1 + N4_2 + N4_3)

__global__ void cvt_all(const float4* __restrict__ w0, const float4* __restrict__ w1,
                        const float4* __restrict__ w2, const float4* __restrict__ w3,
                        __half2* __restrict__ o0, __half2* __restrict__ o1,
                        __half2* __restrict__ o2, __half2* __restrict__ o3) {
    int i = blockIdx.x * 256 + threadIdx.x;
    const float4* src;
    __half2* dst;
    int j = i;
    if (j < N4_0)                { src = w0; dst = o0; }
    else if ((j -= N4_0) < N4_1) { src = w1; dst = o1; }
    else if ((j -= N4_1) < N4_2) { src = w2; dst = o2; }
    else if ((j -= N4_2) < N4_3) { src = w3; dst = o3; }
    else return;
    float4 v = src[j];
    dst[j * 2]     = __floats2half2_rn(v.x, v.y);
    dst[j * 2 + 1] = __floats2half2_rn(v.z, v.w);
}

// ---------------- LayerNorm: warp per row, shfl-only reductions -------------------
__global__ void __launch_bounds__(256) ln_kernel(
    const float* __restrict__ x, const float* __restrict__ w,
    const float* __restrict__ bb, __half* __restrict__ y)
{
    const int warp = threadIdx.x >> 5, lane = threadIdx.x & 31;
    const size_t row = (size_t)blockIdx.x * 8 + warp;
    const float* xr = x + row * D_;

    float4 v[6];
    float s = 0.f;
    #pragma unroll
    for (int i = 0; i < 6; i++) {
        v[i] = *(const float4*)(xr + (i * 32 + lane) * 4);
        s += v[i].x + v[i].y + v[i].z + v[i].w;
    }
    #pragma unroll
    for (int o = 16; o > 0; o >>= 1) s += __shfl_xor_sync(0xffffffffu, s, o);
    const float mu = s * (1.f / 768.f);

    float vs = 0.f;
    #pragma unroll
    for (int i = 0; i < 6; i++) {
        v[i].x -= mu; v[i].y -= mu; v[i].z -= mu; v[i].w -= mu;
        vs += v[i].x * v[i].x + v[i].y * v[i].y + v[i].z * v[i].z + v[i].w * v[i].w;
    }
    #pragma unroll
    for (int o = 16; o > 0; o >>= 1) vs += __shfl_xor_sync(0xffffffffu, vs, o);
    const float rstd = rsqrtf(vs * (1.f / 768.f) + 1e-5f);

    __half* yr = y + row * D_;
    #pragma unroll
    for (int i = 0; i < 6; i++) {
        int c = (i * 32 + lane) * 4;
        float4 wv = *(const float4*)(w + c);
        float4 bv = *(const float4*)(bb + c);
        __half2 h0 = __floats2half2_rn(v[i].x * rstd * wv.x + bv.x,
                                       v[i].y * rstd * wv.y + bv.y);
        __half2 h1 = __floats2half2_rn(v[i].z * rstd * wv.z + bv.z,
                                       v[i].w * rstd * wv.w + bv.w);
        uint2 pack = {h2u(h0), h2u(h1)};
        *(uint2*)(yr + c) = pack;
    }
}

// ---------------- Attention: fp16 TC flash, ex2.f16x2 softmax, MMA lsum ----------
#define TQ 128
#define QPH 72
#define KPH 72
#define VPH 72
#define KV_SLOT (64 * KPH + 64 * VPH)
#define ATTN_SMEM_BYTES ((128 * QPH + 3 * KV_SLOT) * 2 + 3 * 64 * 4 + 3 * 2 * 4 + 64)

__global__ void __launch_bounds__(256, 2) attn_h_kernel(
    const __half* __restrict__ qkv, const int* __restrict__ amask,
    __half* __restrict__ out)
{
    extern __shared__ char dynsm[];
    __half* Qs = (__half*)dynsm;
    __half* KV = Qs + 128 * QPH;
    int* kmsk  = (int*)(KV + 3 * KV_SLOT);
    int* mflag = kmsk + 3 * 64;

    const int qi = blockIdx.x, h = blockIdx.y, b = blockIdx.z;
    const int qb = qi * TQ;
    const int tid = threadIdx.x, wid = tid >> 5, lane = tid & 31;
    const int lr = lane >> 2, lc = lane & 3;
    const int wq = wid * 16;
    const int sel = lane >> 3;
    const int vrow = (sel & 1) * 8 + (lane & 7);
    const int vcol = (sel >> 1) * 8;
    const int krow = (lane & 7) + ((lane >> 4) << 3);
    const int kcol = ((lane >> 3) & 1) * 8;

    {
        int r = tid >> 1, cb = (tid & 1) * 32;
        const __half* src = qkv + (size_t)(b * T_ + qb + r) * (3 * D_) + h * 64 + cb;
        #pragma unroll
        for (int c = 0; c < 4; c++)
            *(uint4*)(Qs + r * QPH + cb + c * 8) = *(const uint4*)(src + c * 8);
    }

    int lo = qb - (WIN_ - 1);
    const int kt0 = (lo > 0 ? lo : 0) >> 6;
    const int kt1 = (qb + TQ - 1) >> 6;

    const int lrr = tid >> 2, lcb = (tid & 3) * 16;
    auto load_kv = [&](int s, int kt) {
        const int kb = kt * 64;
        __half* Kb = KV + s * KV_SLOT;
        __half* Vb = Kb + 64 * KPH;
        const __half* kp = qkv + (size_t)(b * T_ + kb + lrr) * (3 * D_) + D_ + h * 64 + lcb;
        uint32_t ka = smem_to_u32(Kb + lrr * KPH + lcb);
        uint32_t va = smem_to_u32(Vb + lrr * VPH + lcb);
        CP16(ka, kp);           CP16(ka + 16, kp + 8);
        CP16(va, kp + D_);      CP16(va + 16, kp + D_ + 8);
        if (tid < 64) {
            Vb[tid * VPH + 64] = __float2half(1.f);
            int mv = amask[b * T_ + kb + tid];
            kmsk[s * 64 + tid] = mv;
            unsigned bal = __ballot_sync(0xffffffffu, mv != 0);
            if ((tid & 31) == 0) mflag[s * 2 + (tid >> 5)] = (bal == 0xffffffffu);
        }
    };

    load_kv(0, kt0); CP_COMMIT();
    if (kt0 + 1 <= kt1) load_kv(1, kt0 + 1);
    CP_COMMIT();

    __syncthreads();
    const __half2 sc2 = __floats2half2_rn(0.125f, 0.125f);
    uint32_t qa[4][4];
    #pragma unroll
    for (int kk = 0; kk < 4; kk++) {
        const __half* p = Qs + (size_t)(wq + lr) * QPH + kk * 16 + lc * 2;
        qa[kk][0] = h2u(__hmul2(*(const __half2*)p, sc2));
        qa[kk][1] = h2u(__hmul2(*(const __half2*)(p + 8 * QPH), sc2));
        qa[kk][2] = h2u(__hmul2(*(const __half2*)(p + 8), sc2));
        qa[kk][3] = h2u(__hmul2(*(const __half2*)(p + 8 * QPH + 8), sc2));
    }

    float o[8][4];
    #pragma unroll
    for (int j = 0; j < 8; j++)
        #pragma unroll
        for (int k = 0; k < 4; k++) o[j][k] = 0.f;
    float mrow[2] = {MASKNEG, MASKNEG}, lrow[2] = {0.f, 0.f};
    const float L2E = 1.4426950408889634f;

    for (int kt = kt0; kt <= kt1; kt++) {
        const int kb = kt * 64;
        const int s = (kt - kt0) % 3;

        CP_WAIT1();
        __syncthreads();
        if (kt + 2 <= kt1) load_kv((kt - kt0 + 2) % 3, kt + 2);
        CP_COMMIT();

        const bool warp_active = (kb <= qb + wq + 15) && (kb + 63 > qb + wq - WIN_);
        if (warp_active) {
            const __half* Kb = KV + s * KV_SLOT;
            const __half* Vb = Kb + 64 * KPH;
            const int* km = kmsk + s * 64;
            const bool tilefull = (kb + 63 <= qb + wq) && (kb >= qb + wq - 752) &&
                                  mflag[s * 2] && mflag[s * 2 + 1];

            float sv[8][4];
            #pragma unroll
            for (int j = 0; j < 8; j++)
                sv[j][0] = sv[j][1] = sv[j][2] = sv[j][3] = 0.f;
            const uint32_t kbase = smem_to_u32(Kb);
            #pragma unroll
            for (int jp = 0; jp < 4; jp++) {
                #pragma unroll
                for (int kk = 0; kk < 4; kk++) {
                    uint32_t kb4[4];
                    uint32_t addr = kbase + ((jp * 16 + krow) * KPH + kk * 16 + kcol) * 2;
                    LDSM4(kb4[0], kb4[1], kb4[2], kb4[3], addr);
                    mma1616(sv[jp * 2],     qa[kk], kb4);
                    mma1616(sv[jp * 2 + 1], qa[kk], kb4 + 2);
                }
            }

            if (!tilefull) {
                #pragma unroll
                for (int j = 0; j < 8; j++) {
                    int kg0 = kb + j * 8 + lc * 2, kg1 = kg0 + 1;
                    int km0 = km[j * 8 + lc * 2], km1 = km[j * 8 + lc * 2 + 1];
                    #pragma unroll
                    for (int half = 0; half < 2; half++) {
                        int qg = qb + wq + lr + half * 8;
                        bool v0 = (kg0 <= qg) && (kg0 > qg - WIN_) && (km0 != 0);
                        bool v1 = (kg1 <= qg) && (kg1 > qg - WIN_) && (km1 != 0);
                        if (!v0) sv[j][half * 2 + 0] = MASKNEG;
                        if (!v1) sv[j][half * 2 + 1] = MASKNEG;
                    }
                }
            }

            float mnew[2], alpha[2];
            #pragma unroll
            for (int half = 0; half < 2; half++) {
                float m = MASKNEG;
                #pragma unroll
                for (int j = 0; j < 8; j++)
                    m = fmaxf(m, fmaxf(sv[j][half * 2], sv[j][half * 2 + 1]));
                m = fmaxf(m, __shfl_xor_sync(0xffffffffu, m, 1));
                m = fmaxf(m, __shfl_xor_sync(0xffffffffu, m, 2));
                mnew[half] = fmaxf(mrow[half], m);
                alpha[half] = __expf(mrow[half] - mnew[half]);
            }

            const float nm0 = mnew[0] * L2E, nm1 = mnew[1] * L2E;
            uint32_t pu[8][2];
            #pragma unroll
            for (int j = 0; j < 8; j++) {
                float t0 = fmaf(sv[j][0], L2E, -nm0);
                float t1 = fmaf(sv[j][1], L2E, -nm0);
                float t2 = fmaf(sv[j][2], L2E, -nm1);
                float t3 = fmaf(sv[j][3], L2E, -nm1);
                pu[j][0] = ex2_h2(h2u(__floats2half2_rn(t0, t1)));
                pu[j][1] = ex2_h2(h2u(__floats2half2_rn(t2, t3)));
            }

            #pragma unroll
            for (int j = 0; j < 8; j++) {
                o[j][0] *= alpha[0]; o[j][1] *= alpha[0];
                o[j][2] *= alpha[1]; o[j][3] *= alpha[1];
            }

            float ls[4] = {0.f, 0.f, 0.f, 0.f};
            const uint32_t vbase = smem_to_u32(Vb);
            #pragma unroll
            for (int kk = 0; kk < 4; kk++) {
                uint32_t pa[4] = {pu[2 * kk][0], pu[2 * kk][1],
                                  pu[2 * kk + 1][0], pu[2 * kk + 1][1]};
                #pragma unroll
                for (int jp = 0; jp < 4; jp++) {
                    uint32_t vb[4];
                    uint32_t addr = vbase + ((kk * 16 + vrow) * VPH + jp * 16 + vcol) * 2;
                    LDSM4T(vb[0], vb[1], vb[2], vb[3], addr);
                    mma1616(o[jp * 2],     pa, vb);
                    mma1616(o[jp * 2 + 1], pa, vb + 2);
                }
                uint32_t vb1[4];
                uint32_t addr1 = vbase + ((kk * 16 + vrow) * VPH + 64 + vcol) * 2;
                LDSM4T(vb1[0], vb1[1], vb1[2], vb1[3], addr1);
                mma1616(ls, pa, vb1);
            }
            float l0 = __shfl_sync(0xffffffffu, ls[0], lane & 0x1c);
            float l1 = __shfl_sync(0xffffffffu, ls[2], lane & 0x1c);
            lrow[0] = lrow[0] * alpha[0] + l0;
            lrow[1] = lrow[1] * alpha[1] + l1;
            mrow[0] = mnew[0];
            mrow[1] = mnew[1];
        }
    }

    float linv[2] = {1.f / lrow[0], 1.f / lrow[1]};
    #pragma unroll
    for (int half = 0; half < 2; half++) {
        size_t row = (size_t)(b * T_ + qb + wq + lr + half * 8);
        __half* op = out + row * D_ + h * 64;
        #pragma unroll
        for (int j = 0; j < 8; j++)
            *(__half2*)(op + j * 8 + lc * 2) =
                __floats2half2_rn(o[j][half * 2] * linv[half], o[j][half * 2 + 1] * linv[half]);
    }
}

// ---------------- launch -----------------------------------------------------------
extern "C" void kernel_launch(void* const* d_in, const int* in_sizes, int n_in,
                              void* d_out, int out_size)
{
    const float* x      = (const float*)d_in[0];
    const int*   amask  = (const int*)d_in[1];
    const float* ln1_w  = (const float*)d_in[2];
    const float* ln1_b  = (const float*)d_in[3];
    const float* w_attn = (const float*)d_in[4];
    const float* b_attn = (const float*)d_in[5];
    const float* w_proj = (const float*)d_in[6];
    const float* b_proj = (const float*)d_in[7];
    const float* ln2_w  = (const float*)d_in[8];
    const float* ln2_b  = (const float*)d_in[9];
    const float* w_fc   = (const float*)d_in[10];
    const float* b_fc   = (const float*)d_in[11];
    const float* w_fcp  = (const float*)d_in[12];
    const float* b_fcp  = (const float*)d_in[13];
    float* out = (float*)d_out;

    __half *p_x1h, *p_qkvh, *p_attnh, *p_hh, *p_wah, *p_wph, *p_wfh, *p_wfph;
    float* p_x2;
    cudaGetSymbolAddress((void**)&p_x1h,   g_x1h);
    cudaGetSymbolAddress((void**)&p_qkvh,  g_qkvh);
    cudaGetSymbolAddress((void**)&p_attnh, g_attnh);
    cudaGetSymbolAddress((void**)&p_x2,    g_x2);
    cudaGetSymbolAddress((void**)&p_hh,    g_hh);
    cudaGetSymbolAddress((void**)&p_wah,   g_wah);
    cudaGetSymbolAddress((void**)&p_wph,   g_wph);
    cudaGetSymbolAddress((void**)&p_wfh,   g_wfh);
    cudaGetSymbolAddress((void**)&p_wfph,  g_wfph);

    cudaFuncSetAttribute(hgemm<EPI_BIAS, true>,       cudaFuncAttributeMaxDynamicSharedMemorySize, GEMM_SMEM);
    cudaFuncSetAttribute(hgemm<EPI_BIAS_RES, false>,  cudaFuncAttributeMaxDynamicSharedMemorySize, GEMM_SMEM);
    cudaFuncSetAttribute(hgemm<EPI_BIAS_GELU, true>,  cudaFuncAttributeMaxDynamicSharedMemorySize, GEMM_SMEM);
    cudaFuncSetAttribute(hgemm<EPI_RED, false>,       cudaFuncAttributeMaxDynamicSharedMemorySize, GEMM_SMEM);
    cudaFuncSetAttribute(attn_h_kernel, cudaFuncAttributeMaxDynamicSharedMemorySize, ATTN_SMEM_BYTES);

    cvt_all<<<(N4_ALL + 255) / 256, 256>>>(
        (const float4*)w_attn, (const float4*)w_proj, (const float4*)w_fc, (const float4*)w_fcp,
        (__half2*)p_wah, (__half2*)p_wph, (__half2*)p_wfh, (__half2*)p_wfph);

    // 1) ln1 -> fp16
    ln_kernel<<<M_ / 8, 256>>>(x, ln1_w, ln1_b, p_x1h);
    // 2) qkv = x1 @ w_attn + b_attn
    hgemm<EPI_BIAS, true><<<dim3(2304 / 128, M_ / 128), 256, GEMM_SMEM>>>(
        p_x1h, p_wah, b_attn, nullptr, nullptr, p_qkvh, 2304, 768, 768);
    // 3) attention
    attn_h_kernel<<<dim3(T_ / TQ, H_, B_), 256, ATTN_SMEM_BYTES>>>(p_qkvh, amask, p_attnh);
    // 4) x2 = attn @ w_proj + b_proj + x
    hgemm<EPI_BIAS_RES, false><<<dim3(768 / 128, M_ / 128), 256, GEMM_SMEM>>>(
        p_attnh, p_wph, b_proj, x, p_x2, nullptr, 768, 768, 768);
    // 4b) out = x2 + b_fcp  (base for split-K reduction; off critical path)
    init_out_kernel<<<M_ * D_ / 4 / 256, 256>>>((const float4*)p_x2, b_fcp, (float4*)out);
    // 5) ln2 -> fp16
    ln_kernel<<<M_ / 8, 256>>>(p_x2, ln2_w, ln2_b, p_x1h);
    // 6) h = gelu(x1 @ w_fc + b_fc)
    hgemm<EPI_BIAS_GELU, true><<<dim3(3072 / 128, M_ / 128), 256, GEMM_SMEM>>>(
        p_x1h, p_wfh, b_fc, nullptr, nullptr, p_hh, 3072, 768, 768);
    // 7) out += h @ w_fc_proj   (split-K x2, atomic reduction)
    hgemm<EPI_RED, false><<<dim3(768 / 128, M_ / 128, 2), 256, GEMM_SMEM>>>(
        p_hh, p_wfph, nullptr, nullptr, out, nullptr, 768, 1536, 3072);
}

// round 16
// speedup vs baseline: 1.1066x; 1.0063x over previous
#include <cuda_runtime.h>
#include <cuda_fp16.h>
#include <math.h>
#include <stdint.h>

#define B_   8
#define T_   1024
#define D_   768
#define H_   12
#define WIN_ 768
#define M_   (B_*T_)   // 8192
#define MASKNEG (-60000.0f)

// ---------------- scratch (static device globals) ---------------------------
__device__ __half g_x1h[M_ * D_];
__device__ __half g_qkvh[M_ * 3 * D_];
__device__ __half g_attnh[M_ * D_];
__device__ float  g_x2[M_ * D_];
__device__ __half g_hh[M_ * 4 * D_];
__device__ __half g_wah[D_ * 3 * D_];
__device__ __half g_wph[D_ * D_];
__device__ __half g_wfh[D_ * 4 * D_];
__device__ __half g_wfph[4 * D_ * D_];

// ---------------- helpers -----------------------------------------------------
__device__ __forceinline__ uint32_t smem_to_u32(const void* p) {
    uint32_t a;
    asm("{ .reg .u64 t; cvta.to.shared.u64 t, %1; cvt.u32.u64 %0, t; }" : "=r"(a) : "l"(p));
    return a;
}
__device__ __forceinline__ uint32_t h2u(__half2 v) { return *(uint32_t*)&v; }

#define CP16(saddr, gptr) \
    asm volatile("cp.async.cg.shared.global [%0], [%1], 16;" :: "r"(saddr), "l"(gptr))
#define CP_COMMIT() asm volatile("cp.async.commit_group;" ::: "memory")
#define CP_WAIT2()  asm volatile("cp.async.wait_group 2;" ::: "memory")
#define CP_WAIT1()  asm volatile("cp.async.wait_group 1;" ::: "memory")

#define LDSM4(r0, r1, r2, r3, addr) \
    asm volatile("ldmatrix.sync.aligned.m8n8.x4.shared.b16 {%0,%1,%2,%3}, [%4];" \
        : "=r"(r0), "=r"(r1), "=r"(r2), "=r"(r3) : "r"(addr))
#define LDSM4T(r0, r1, r2, r3, addr) \
    asm volatile("ldmatrix.sync.aligned.m8n8.x4.trans.shared.b16 {%0,%1,%2,%3}, [%4];" \
        : "=r"(r0), "=r"(r1), "=r"(r2), "=r"(r3) : "r"(addr))

__device__ __forceinline__ void mma1616(float* d, const uint32_t* a, const uint32_t* b) {
    asm volatile(
        "mma.sync.aligned.m16n8k16.row.col.f32.f16.f16.f32 "
        "{%0,%1,%2,%3}, {%4,%5,%6,%7}, {%8,%9}, {%0,%1,%2,%3};"
        : "+f"(d[0]), "+f"(d[1]), "+f"(d[2]), "+f"(d[3])
        : "r"(a[0]), "r"(a[1]), "r"(a[2]), "r"(a[3]), "r"(b[0]), "r"(b[1]));
}
__device__ __forceinline__ uint32_t ex2_h2(uint32_t x) {
    uint32_t r;
    asm("ex2.approx.f16x2 %0, %1;" : "=r"(r) : "r"(x));
    return r;
}

// ---------------- fp16 tensor-core GEMM (128x128, BK=32, 4 stages) --------------
// EPI_RED: split-K partial, atomicAdd into pre-initialized C.
// EPI_RES_DUAL: v = acc + bias + R -> Cf; also Cf2 = v + bias2 (fused out-init).
enum { EPI_BIAS = 0, EPI_BIAS_RES = 1, EPI_BIAS_GELU = 2, EPI_RED = 3, EPI_RES_DUAL = 4 };

#define NSTG 4
#define APADH 40
#define BPADH 136
#define A_ST (128 * APADH)
#define B_ST (32 * BPADH)
#define STG_H (A_ST + B_ST)
#define GEMM_SMEM (NSTG * STG_H * 2)

template <int EPI, bool OUTH>
__global__ void __launch_bounds__(256, 2) hgemm(
    const __half* __restrict__ A, const __half* __restrict__ W,
    const float* __restrict__ bias, const float* __restrict__ R,
    float* __restrict__ Cf, __half* __restrict__ Ch,
    float* __restrict__ Cf2, const float* __restrict__ bias2,
    int N, int K, int Kstride)
{
    extern __shared__ char dynsm[];
    __half* smh = (__half*)dynsm;
    const int tid = threadIdx.x;
    const int wid = tid >> 5, lane = tid & 31;
    const int wm = wid >> 2, wn = wid & 3;
    const int bm = blockIdx.y << 7, bn = blockIdx.x << 7;
    const int koff = blockIdx.z * K;
    const int lr = lane >> 2, lc = lane & 3;
    const int arow = lane & 15, acol8 = (lane >> 4) * 8;
    const int sel = lane >> 3;
    const int brow = (sel & 1) * 8 + (lane & 7), bcol = (sel >> 1) * 8;
    const int NIT = K >> 5;

    const int am = tid >> 1, ac = tid & 1;
    const int br = tid >> 4, bc = tid & 15;
    const __half* gA = A + (size_t)(bm + am) * Kstride + koff;
    const __half* gB = W + (size_t)(koff + br) * N + bn;

    float acc[4][4][4];
    #pragma unroll
    for (int i = 0; i < 4; i++)
        #pragma unroll
        for (int j = 0; j < 4; j++)
            #pragma unroll
            for (int k = 0; k < 4; k++) acc[i][j][k] = 0.f;

    auto load_stage = [&](int s, int kt) {
        __half* Ah = smh + s * STG_H;
        __half* Bh = Ah + A_ST;
        uint32_t sa = smem_to_u32(Ah + am * APADH + ac * 16);
        const __half* ga = gA + (kt << 5) + ac * 16;
        CP16(sa, ga);
        CP16(sa + 16, ga + 8);
        uint32_t sb = smem_to_u32(Bh + br * BPADH + bc * 8);
        const __half* gb = gB + (size_t)(kt << 5) * N + bc * 8;
        CP16(sb, gb);
        CP16(sb + 16 * BPADH * 2, gb + (size_t)16 * N);
    };

    load_stage(0, 0); CP_COMMIT();
    load_stage(1, 1); CP_COMMIT();
    load_stage(2, 2); CP_COMMIT();

    for (int it = 0; it < NIT; it++) {
        CP_WAIT2();
        __syncthreads();
        if (it + 3 < NIT) load_stage((it + 3) % NSTG, it + 3);
        CP_COMMIT();

        const __half* Ah = smh + (it % NSTG) * STG_H;
        const uint32_t abase = smem_to_u32(Ah);
        const uint32_t bbase = smem_to_u32(Ah + A_ST);
        #pragma unroll
        for (int kk = 0; kk < 2; kk++) {
            uint32_t bfr[4][2];
            #pragma unroll
            for (int ntp = 0; ntp < 2; ntp++) {
                uint32_t addr = bbase +
                    ((kk * 16 + brow) * BPADH + wn * 32 + ntp * 16 + bcol) * 2;
                LDSM4T(bfr[ntp * 2][0], bfr[ntp * 2][1],
                       bfr[ntp * 2 + 1][0], bfr[ntp * 2 + 1][1], addr);
            }
            #pragma unroll
            for (int mt = 0; mt < 4; mt++) {
                uint32_t af[4];
                uint32_t aaddr = abase +
                    ((wm * 64 + mt * 16 + arow) * APADH + kk * 16 + acol8) * 2;
                LDSM4(af[0], af[1], af[2], af[3], aaddr);
                #pragma unroll
                for (int nt = 0; nt < 4; nt++)
                    mma1616(acc[mt][nt], af, bfr[nt]);
            }
        }
    }

    #pragma unroll
    for (int mt = 0; mt < 4; mt++) {
        #pragma unroll
        for (int nt = 0; nt < 4; nt++) {
            int col = bn + wn * 32 + nt * 8 + lc * 2;
            float2 bv = {0.f, 0.f};
            if (EPI != EPI_RED) bv = *(const float2*)(bias + col);
            #pragma unroll
            for (int half = 0; half < 2; half++) {
                size_t row = (size_t)(bm + wm * 64 + mt * 16 + lr + half * 8);
                float v0 = acc[mt][nt][half * 2 + 0] + bv.x;
                float v1 = acc[mt][nt][half * 2 + 1] + bv.y;
                if (EPI == EPI_BIAS_RES || EPI == EPI_RES_DUAL) {
                    float2 rv = *(const float2*)(R + row * N + col);
                    v0 += rv.x; v1 += rv.y;
                }
                if (EPI == EPI_BIAS_GELU) {
                    v0 = 0.5f * v0 * (1.f + erff(v0 * 0.7071067811865476f));
                    v1 = 0.5f * v1 * (1.f + erff(v1 * 0.7071067811865476f));
                }
                if (EPI == EPI_RED) {
                    atomicAdd(Cf + row * N + col,     v0);
                    atomicAdd(Cf + row * N + col + 1, v1);
                } else if (OUTH) {
                    *(__half2*)(Ch + row * N + col) = __floats2half2_rn(v0, v1);
                } else {
                    float2 o = {v0, v1};
                    *(float2*)(Cf + row * N + col) = o;
                    if (EPI == EPI_RES_DUAL) {
                        float2 b2 = *(const float2*)(bias2 + col);
                        float2 o2 = {v0 + b2.x, v1 + b2.y};
                        *(float2*)(Cf2 + row * N + col) = o2;
                    }
                }
            }
        }
    }
}

// ---------------- all weights fp32 -> fp16, one launch ---------------------------
#define N4_0 (768 * 2304 / 4)
#define N4_1 (768 * 768 / 4)
#define N4_2 (768 * 3072 / 4)
#define N4_3 (3072 * 768 / 4)
#define N4_ALL (N4_0 + N4_1 + N4_2 + N4_3)

__global__ void cvt_all(const float4* __restrict__ w0, const float4* __restrict__ w1,
                        const float4* __restrict__ w2, const float4* __restrict__ w3,
                        __half2* __restrict__ o0, __half2* __restrict__ o1,
                        __half2* __restrict__ o2, __half2* __restrict__ o3) {
    int i = blockIdx.x * 256 + threadIdx.x;
    const float4* src;
    __half2* dst;
    int j = i;
    if (j < N4_0)                { src = w0; dst = o0; }
    else if ((j -= N4_0) < N4_1) { src = w1; dst = o1; }
    else if ((j -= N4_1) < N4_2) { src = w2; dst = o2; }
    else if ((j -= N4_2) < N4_3) { src = w3; dst = o3; }
    else return;
    float4 v = src[j];
    dst[j * 2]     = __floats2half2_rn(v.x, v.y);
    dst[j * 2 + 1] = __floats2half2_rn(v.z, v.w);
}

// ---------------- LayerNorm: warp per row, shfl-only reductions -------------------
__global__ void __launch_bounds__(256) ln_kernel(
    const float* __restrict__ x, const float* __restrict__ w,
    const float* __restrict__ bb, __half* __restrict__ y)
{
    const int warp = threadIdx.x >> 5, lane = threadIdx.x & 31;
    const size_t row = (size_t)blockIdx.x * 8 + warp;
    const float* xr = x + row * D_;

    float4 v[6];
    float s = 0.f;
    #pragma unroll
    for (int i = 0; i < 6; i++) {
        v[i] = *(const float4*)(xr + (i * 32 + lane) * 4);
        s += v[i].x + v[i].y + v[i].z + v[i].w;
    }
    #pragma unroll
    for (int o = 16; o > 0; o >>= 1) s += __shfl_xor_sync(0xffffffffu, s, o);
    const float mu = s * (1.f / 768.f);

    float vs = 0.f;
    #pragma unroll
    for (int i = 0; i < 6; i++) {
        v[i].x -= mu; v[i].y -= mu; v[i].z -= mu; v[i].w -= mu;
        vs += v[i].x * v[i].x + v[i].y * v[i].y + v[i].z * v[i].z + v[i].w * v[i].w;
    }
    #pragma unroll
    for (int o = 16; o > 0; o >>= 1) vs += __shfl_xor_sync(0xffffffffu, vs, o);
    const float rstd = rsqrtf(vs * (1.f / 768.f) + 1e-5f);

    __half* yr = y + row * D_;
    #pragma unroll
    for (int i = 0; i < 6; i++) {
        int c = (i * 32 + lane) * 4;
        float4 wv = *(const float4*)(w + c);
        float4 bv = *(const float4*)(bb + c);
        __half2 h0 = __floats2half2_rn(v[i].x * rstd * wv.x + bv.x,
                                       v[i].y * rstd * wv.y + bv.y);
        __half2 h1 = __floats2half2_rn(v[i].z * rstd * wv.z + bv.z,
                                       v[i].w * rstd * wv.w + bv.w);
        uint2 pack = {h2u(h0), h2u(h1)};
        *(uint2*)(yr + c) = pack;
    }
}

// ---------------- Attention: fp16 TC flash, ex2.f16x2 softmax, MMA lsum ----------
#define TQ 128
#define QPH 72
#define KPH 72
#define VPH 72
#define KV_SLOT (64 * KPH + 64 * VPH)
#define ATTN_SMEM_BYTES ((128 * QPH + 3 * KV_SLOT) * 2 + 3 * 64 * 4 + 3 * 2 * 4 + 64)

__global__ void __launch_bounds__(256, 2) attn_h_kernel(
    const __half* __restrict__ qkv, const int* __restrict__ amask,
    __half* __restrict__ out)
{
    extern __shared__ char dynsm[];
    __half* Qs = (__half*)dynsm;
    __half* KV = Qs + 128 * QPH;
    int* kmsk  = (int*)(KV + 3 * KV_SLOT);
    int* mflag = kmsk + 3 * 64;

    const int qi = blockIdx.x, h = blockIdx.y, b = blockIdx.z;
    const int qb = qi * TQ;
    const int tid = threadIdx.x, wid = tid >> 5, lane = tid & 31;
    const int lr = lane >> 2, lc = lane & 3;
    const int wq = wid * 16;
    const int sel = lane >> 3;
    const int vrow = (sel & 1) * 8 + (lane & 7);
    const int vcol = (sel >> 1) * 8;
    const int krow = (lane & 7) + ((lane >> 4) << 3);
    const int kcol = ((lane >> 3) & 1) * 8;

    {
        int r = tid >> 1, cb = (tid & 1) * 32;
        const __half* src = qkv + (size_t)(b * T_ + qb + r) * (3 * D_) + h * 64 + cb;
        #pragma unroll
        for (int c = 0; c < 4; c++)
            *(uint4*)(Qs + r * QPH + cb + c * 8) = *(const uint4*)(src + c * 8);
    }

    int lo = qb - (WIN_ - 1);
    const int kt0 = (lo > 0 ? lo : 0) >> 6;
    const int kt1 = (qb + TQ - 1) >> 6;

    const int lrr = tid >> 2, lcb = (tid & 3) * 16;
    auto load_kv = [&](int s, int kt) {
        const int kb = kt * 64;
        __half* Kb = KV + s * KV_SLOT;
        __half* Vb = Kb + 64 * KPH;
        const __half* kp = qkv + (size_t)(b * T_ + kb + lrr) * (3 * D_) + D_ + h * 64 + lcb;
        uint32_t ka = smem_to_u32(Kb + lrr * KPH + lcb);
        uint32_t va = smem_to_u32(Vb + lrr * VPH + lcb);
        CP16(ka, kp);           CP16(ka + 16, kp + 8);
        CP16(va, kp + D_);      CP16(va + 16, kp + D_ + 8);
        if (tid < 64) {
            Vb[tid * VPH + 64] = __float2half(1.f);
            int mv = amask[b * T_ + kb + tid];
            kmsk[s * 64 + tid] = mv;
            unsigned bal = __ballot_sync(0xffffffffu, mv != 0);
            if ((tid & 31) == 0) mflag[s * 2 + (tid >> 5)] = (bal == 0xffffffffu);
        }
    };

    load_kv(0, kt0); CP_COMMIT();
    if (kt0 + 1 <= kt1) load_kv(1, kt0 + 1);
    CP_COMMIT();

    __syncthreads();
    const __half2 sc2 = __floats2half2_rn(0.125f, 0.125f);
    uint32_t qa[4][4];
    #pragma unroll
    for (int kk = 0; kk < 4; kk++) {
        const __half* p = Qs + (size_t)(wq + lr) * QPH + kk * 16 + lc * 2;
        qa[kk][0] = h2u(__hmul2(*(const __half2*)p, sc2));
        qa[kk][1] = h2u(__hmul2(*(const __half2*)(p + 8 * QPH), sc2));
        qa[kk][2] = h2u(__hmul2(*(const __half2*)(p + 8), sc2));
        qa[kk][3] = h2u(__hmul2(*(const __half2*)(p + 8 * QPH + 8), sc2));
    }

    float o[8][4];
    #pragma unroll
    for (int j = 0; j < 8; j++)
        #pragma unroll
        for (int k = 0; k < 4; k++) o[j][k] = 0.f;
    float mrow[2] = {MASKNEG, MASKNEG}, lrow[2] = {0.f, 0.f};
    const float L2E = 1.4426950408889634f;

    for (int kt = kt0; kt <= kt1; kt++) {
        const int kb = kt * 64;
        const int s = (kt - kt0) % 3;

        CP_WAIT1();
        __syncthreads();
        if (kt + 2 <= kt1) load_kv((kt - kt0 + 2) % 3, kt + 2);
        CP_COMMIT();

        const bool warp_active = (kb <= qb + wq + 15) && (kb + 63 > qb + wq - WIN_);
        if (warp_active) {
            const __half* Kb = KV + s * KV_SLOT;
            const __half* Vb = Kb + 64 * KPH;
            const int* km = kmsk + s * 64;
            const bool tilefull = (kb + 63 <= qb + wq) && (kb >= qb + wq - 752) &&
                                  mflag[s * 2] && mflag[s * 2 + 1];

            float sv[8][4];
            #pragma unroll
            for (int j = 0; j < 8; j++)
                sv[j][0] = sv[j][1] = sv[j][2] = sv[j][3] = 0.f;
            const uint32_t kbase = smem_to_u32(Kb);
            #pragma unroll
            for (int jp = 0; jp < 4; jp++) {
                #pragma unroll
                for (int kk = 0; kk < 4; kk++) {
                    uint32_t kb4[4];
                    uint32_t addr = kbase + ((jp * 16 + krow) * KPH + kk * 16 + kcol) * 2;
                    LDSM4(kb4[0], kb4[1], kb4[2], kb4[3], addr);
                    mma1616(sv[jp * 2],     qa[kk], kb4);
                    mma1616(sv[jp * 2 + 1], qa[kk], kb4 + 2);
                }
            }

            if (!tilefull) {
                #pragma unroll
                for (int j = 0; j < 8; j++) {
                    int kg0 = kb + j * 8 + lc * 2, kg1 = kg0 + 1;
                    int km0 = km[j * 8 + lc * 2], km1 = km[j * 8 + lc * 2 + 1];
                    #pragma unroll
                    for (int half = 0; half < 2; half++) {
                        int qg = qb + wq + lr + half * 8;
                        bool v0 = (kg0 <= qg) && (kg0 > qg - WIN_) && (km0 != 0);
                        bool v1 = (kg1 <= qg) && (kg1 > qg - WIN_) && (km1 != 0);
                        if (!v0) sv[j][half * 2 + 0] = MASKNEG;
                        if (!v1) sv[j][half * 2 + 1] = MASKNEG;
                    }
                }
            }

            float mnew[2], alpha[2];
            #pragma unroll
            for (int half = 0; half < 2; half++) {
                float m = MASKNEG;
                #pragma unroll
                for (int j = 0; j < 8; j++)
                    m = fmaxf(m, fmaxf(sv[j][half * 2], sv[j][half * 2 + 1]));
                m = fmaxf(m, __shfl_xor_sync(0xffffffffu, m, 1));
                m = fmaxf(m, __shfl_xor_sync(0xffffffffu, m, 2));
                mnew[half] = fmaxf(mrow[half], m);
                alpha[half] = __expf(mrow[half] - mnew[half]);
            }

            const float nm0 = mnew[0] * L2E, nm1 = mnew[1] * L2E;
            uint32_t pu[8][2];
            #pragma unroll
            for (int j = 0; j < 8; j++) {
                float t0 = fmaf(sv[j][0], L2E, -nm0);
                float t1 = fmaf(sv[j][1], L2E, -nm0);
                float t2 = fmaf(sv[j][2], L2E, -nm1);
                float t3 = fmaf(sv[j][3], L2E, -nm1);
                pu[j][0] = ex2_h2(h2u(__floats2half2_rn(t0, t1)));
                pu[j][1] = ex2_h2(h2u(__floats2half2_rn(t2, t3)));
            }

            #pragma unroll
            for (int j = 0; j < 8; j++) {
                o[j][0] *= alpha[0]; o[j][1] *= alpha[0];
                o[j][2] *= alpha[1]; o[j][3] *= alpha[1];
            }

            float ls[4] = {0.f, 0.f, 0.f, 0.f};
            const uint32_t vbase = smem_to_u32(Vb);
            #pragma unroll
            for (int kk = 0; kk < 4; kk++) {
                uint32_t pa[4] = {pu[2 * kk][0], pu[2 * kk][1],
                                  pu[2 * kk + 1][0], pu[2 * kk + 1][1]};
                #pragma unroll
                for (int jp = 0; jp < 4; jp++) {
                    uint32_t vb[4];
                    uint32_t addr = vbase + ((kk * 16 + vrow) * VPH + jp * 16 + vcol) * 2;
                    LDSM4T(vb[0], vb[1], vb[2], vb[3], addr);
                    mma1616(o[jp * 2],     pa, vb);
                    mma1616(o[jp * 2 + 1], pa, vb + 2);
                }
                uint32_t vb1[4];
                uint32_t addr1 = vbase + ((kk * 16 + vrow) * VPH + 64 + vcol) * 2;
                LDSM4T(vb1[0], vb1[1], vb1[2], vb1[3], addr1);
                mma1616(ls, pa, vb1);
            }
            float l0 = __shfl_sync(0xffffffffu, ls[0], lane & 0x1c);
            float l1 = __shfl_sync(0xffffffffu, ls[2], lane & 0x1c);
            lrow[0] = lrow[0] * alpha[0] + l0;
            lrow[1] = lrow[1] * alpha[1] + l1;
            mrow[0] = mnew[0];
            mrow[1] = mnew[1];
        }
    }

    float linv[2] = {1.f / lrow[0], 1.f / lrow[1]};
    #pragma unroll
    for (int half = 0; half < 2; half++) {
        size_t row = (size_t)(b * T_ + qb + wq + lr + half * 8);
        __half* op = out + row * D_ + h * 64;
        #pragma unroll
        for (int j = 0; j < 8; j++)
            *(__half2*)(op + j * 8 + lc * 2) =
                __floats2half2_rn(o[j][half * 2] * linv[half], o[j][half * 2 + 1] * linv[half]);
    }
}

// ---------------- launch -----------------------------------------------------------
extern "C" void kernel_launch(void* const* d_in, const int* in_sizes, int n_in,
                              void* d_out, int out_size)
{
    const float* x      = (const float*)d_in[0];
    const int*   amask  = (const int*)d_in[1];
    const float* ln1_w  = (const float*)d_in[2];
    const float* ln1_b  = (const float*)d_in[3];
    const float* w_attn = (const float*)d_in[4];
    const float* b_attn = (const float*)d_in[5];
    const float* w_proj = (const float*)d_in[6];
    const float* b_proj = (const float*)d_in[7];
    const float* ln2_w  = (const float*)d_in[8];
    const float* ln2_b  = (const float*)d_in[9];
    const float* w_fc   = (const float*)d_in[10];
    const float* b_fc   = (const float*)d_in[11];
    const float* w_fcp  = (const float*)d_in[12];
    const float* b_fcp  = (const float*)d_in[13];
    float* out = (float*)d_out;

    __half *p_x1h, *p_qkvh, *p_attnh, *p_hh, *p_wah, *p_wph, *p_wfh, *p_wfph;
    float* p_x2;
    cudaGetSymbolAddress((void**)&p_x1h,   g_x1h);
    cudaGetSymbolAddress((void**)&p_qkvh,  g_qkvh);
    cudaGetSymbolAddress((void**)&p_attnh, g_attnh);
    cudaGetSymbolAddress((void**)&p_x2,    g_x2);
    cudaGetSymbolAddress((void**)&p_hh,    g_hh);
    cudaGetSymbolAddress((void**)&p_wah,   g_wah);
    cudaGetSymbolAddress((void**)&p_wph,   g_wph);
    cudaGetSymbolAddress((void**)&p_wfh,   g_wfh);
    cudaGetSymbolAddress((void**)&p_wfph,  g_wfph);

    cudaFuncSetAttribute(hgemm<EPI_BIAS, true>,       cudaFuncAttributeMaxDynamicSharedMemorySize, GEMM_SMEM);
    cudaFuncSetAttribute(hgemm<EPI_RES_DUAL, false>,  cudaFuncAttributeMaxDynamicSharedMemorySize, GEMM_SMEM);
    cudaFuncSetAttribute(hgemm<EPI_BIAS_GELU, true>,  cudaFuncAttributeMaxDynamicSharedMemorySize, GEMM_SMEM);
    cudaFuncSetAttribute(hgemm<EPI_RED, false>,       cudaFuncAttributeMaxDynamicSharedMemorySize, GEMM_SMEM);
    cudaFuncSetAttribute(attn_h_kernel, cudaFuncAttributeMaxDynamicSharedMemorySize, ATTN_SMEM_BYTES);

    cvt_all<<<(N4_ALL + 255) / 256, 256>>>(
        (const float4*)w_attn, (const float4*)w_proj, (const float4*)w_fc, (const float4*)w_fcp,
        (__half2*)p_wah, (__half2*)p_wph, (__half2*)p_wfh, (__half2*)p_wfph);

    // 1) ln1 -> fp16
    ln_kernel<<<M_ / 8, 256>>>(x, ln1_w, ln1_b, p_x1h);
    // 2) qkv = x1 @ w_attn + b_attn
    hgemm<EPI_BIAS, true><<<dim3(2304 / 128, M_ / 128), 256, GEMM_SMEM>>>(
        p_x1h, p_wah, b_attn, nullptr, nullptr, p_qkvh, nullptr, nullptr, 2304, 768, 768);
    // 3) attention
    attn_h_kernel<<<dim3(T_ / TQ, H_, B_), 256, ATTN_SMEM_BYTES>>>(p_qkvh, amask, p_attnh);
    // 4) x2 = attn @ w_proj + b_proj + x ; fused: out = x2 + b_fcp
    hgemm<EPI_RES_DUAL, false><<<dim3(768 / 128, M_ / 128), 256, GEMM_SMEM>>>(
        p_attnh, p_wph, b_proj, x, p_x2, nullptr, out, b_fcp, 768, 768, 768);
    // 5) ln2 -> fp16
    ln_kernel<<<M_ / 8, 256>>>(p_x2, ln2_w, ln2_b, p_x1h);
    // 6) h = gelu(x1 @ w_fc + b_fc)
    hgemm<EPI_BIAS_GELU, true><<<dim3(3072 / 128, M_ / 128), 256, GEMM_SMEM>>>(
        p_x1h, p_wfh, b_fc, nullptr, nullptr, p_hh, nullptr, nullptr, 3072, 768, 768);
    // 7) out += h @ w_fc_proj   (split-K x2, atomic reduction)
    hgemm<EPI_RED, false><<<dim3(768 / 128, M_ / 128, 2), 256, GEMM_SMEM>>>(
        p_hh, p_wfph, nullptr, nullptr, out, nullptr, nullptr, nullptr, 768, 1536, 3072);
}